// round 8
// baseline (speedup 1.0000x reference)
#include <cuda_runtime.h>
#include <cuda_bf16.h>
#include <math.h>
#include <stdint.h>

// Problem constants
#define B 8
#define L 2500
#define D 512
#define Y 8921
#define LP 2560            // L padded (K of GEMM2)

// GEMM geometry: CTA tile 128(M) x 128(N), K-chunk 32, 8 warps (32x64 each),
// 2 CTAs per SM (independent barrier domains).
#define KC 32
#define AH_OFF 0
#define AL_OFF 8192
#define BH_OFF 16384
#define BL_OFF 24576
#define STAGE_BYTES 32768            // Ah+Al+Bh+Bl (each 128x32 bf16 = 8KB)
#define NSTAGE 3
#define SMEM_BYTES (NSTAGE * STAGE_BYTES)   // 98304 per CTA; 2 CTAs = 192KB/SM

// ---------------------------------------------------------------------------
// Device scratch (no cudaMalloc allowed)
// ---------------------------------------------------------------------------
__device__ __align__(16) __nv_bfloat16 g_x_hi[(size_t)B * L * D];
__device__ __align__(16) __nv_bfloat16 g_x_lo[(size_t)B * L * D];
__device__ __align__(16) __nv_bfloat16 g_xT_hi[(size_t)B * D * LP];
__device__ __align__(16) __nv_bfloat16 g_xT_lo[(size_t)B * D * LP];
__device__ __align__(16) __nv_bfloat16 g_U_hi[(size_t)Y * D];
__device__ __align__(16) __nv_bfloat16 g_U_lo[(size_t)Y * D];
__device__ __align__(16) __nv_bfloat16 g_a_hi[(size_t)B * Y * LP];
__device__ __align__(16) __nv_bfloat16 g_a_lo[(size_t)B * Y * LP];
__device__ float g_bce[B * Y];

// ---------------------------------------------------------------------------
// PTX helpers (base sm_103-legal)
// ---------------------------------------------------------------------------
__device__ __forceinline__ uint32_t smem_u32(const void* p) {
    uint32_t a;
    asm("{ .reg .u64 t; cvta.to.shared.u64 t, %1; cvt.u32.u64 %0, t; }"
        : "=r"(a) : "l"(p));
    return a;
}
__device__ __forceinline__ void cpa16(uint32_t dst, const void* src, int szbytes) {
    asm volatile("cp.async.cg.shared.global [%0], [%1], 16, %2;"
                 :: "r"(dst), "l"(src), "r"(szbytes) : "memory");
}
__device__ __forceinline__ void cpa_commit() {
    asm volatile("cp.async.commit_group;" ::: "memory");
}
template <int N>
__device__ __forceinline__ void cpa_wait() {
    asm volatile("cp.async.wait_group %0;" :: "n"(N) : "memory");
}
__device__ __forceinline__ void ldsm4(uint32_t* r, uint32_t addr) {
    asm volatile("ldmatrix.sync.aligned.m8n8.x4.shared.b16 {%0,%1,%2,%3}, [%4];"
                 : "=r"(r[0]), "=r"(r[1]), "=r"(r[2]), "=r"(r[3]) : "r"(addr));
}
__device__ __forceinline__ void mma16816(float* c, const uint32_t* a,
                                         uint32_t b0, uint32_t b1) {
    asm volatile(
        "mma.sync.aligned.m16n8k16.row.col.f32.bf16.bf16.f32 "
        "{%0,%1,%2,%3}, {%4,%5,%6,%7}, {%8,%9}, {%0,%1,%2,%3};"
        : "+f"(c[0]), "+f"(c[1]), "+f"(c[2]), "+f"(c[3])
        : "r"(a[0]), "r"(a[1]), "r"(a[2]), "r"(a[3]), "r"(b0), "r"(b1));
}

// 64B-row XOR swizzle: row r, 16B-chunk c (0..3)
__device__ __forceinline__ uint32_t swz64(int r, int c) {
    return (uint32_t)(r * 64 + ((c ^ ((r >> 1) & 3)) << 4));
}

// ---------------------------------------------------------------------------
// Chunk loader: Ah/Al + Bh/Bl, each 128 x 32 bf16, cp.async 16B. 256 threads,
// 8 cp.async per thread.
// ---------------------------------------------------------------------------
__device__ __forceinline__ void load_chunk(uint32_t st, int kt,
        const __nv_bfloat16* __restrict__ Ah, const __nv_bfloat16* __restrict__ Al,
        size_t sA, int nA,
        const __nv_bfloat16* __restrict__ Bh, const __nv_bfloat16* __restrict__ Bl,
        size_t sB, int nB, int tid) {
#pragma unroll
    for (int it = 0; it < 2; it++) {
        int idx = tid + it * 256;
        int r = idx >> 2, c = idx & 3;
        uint32_t o = swz64(r, c);
        bool ok = r < nA;
        size_t so = ok ? ((size_t)r * sA + kt + c * 8) : 0;
        cpa16(st + AH_OFF + o, Ah + so, ok ? 16 : 0);
        cpa16(st + AL_OFF + o, Al + so, ok ? 16 : 0);
    }
#pragma unroll
    for (int it = 0; it < 2; it++) {
        int idx = tid + it * 256;
        int r = idx >> 2, c = idx & 3;
        uint32_t o = swz64(r, c);
        bool ok = r < nB;
        size_t so = ok ? ((size_t)r * sB + kt + c * 8) : 0;
        cpa16(st + BH_OFF + o, Bh + so, ok ? 16 : 0);
        cpa16(st + BL_OFF + o, Bl + so, ok ? 16 : 0);
    }
}

// ---------------------------------------------------------------------------
// Core GEMM: C[m<=128, n<=128] = sum_k (Ah+Al)[m,k]*(Bh+Bl)[n,k] (drop lo*lo)
// 256 threads, 8 warps 4(M) x 2(N), warp tile 32x64, m16n8k16 bf16.
// 3-stage cp.async ring, one barrier per chunk, B-frag register double-buffer.
// MMAs ordered per-pass so same-accumulator reuse distance is 4 (no RAW stall).
// ---------------------------------------------------------------------------
template <int CHUNKS>
__device__ __forceinline__ void gemm_core(
    const __nv_bfloat16* __restrict__ Ah, const __nv_bfloat16* __restrict__ Al,
    size_t sA, int nA,
    const __nv_bfloat16* __restrict__ Bh, const __nv_bfloat16* __restrict__ Bl,
    size_t sB, int nB,
    float* __restrict__ Co, size_t sC, int nrow, int ncol)
{
    extern __shared__ __align__(128) char smem[];
    const uint32_t sb = smem_u32(smem);
    const int tid = threadIdx.x;
    const int lane = tid & 31;
    const int wid = tid >> 5;
    const int warp_m = wid >> 1;     // 0..3 -> 32-row slabs
    const int warp_n = wid & 1;      // 0..1 -> 64-col slabs

    const int rowsel = lane & 15;
    const int colsel = (lane >> 4) & 1;

    // Per-lane row bases and swizzle keys
    int arb[2], arx[2], brb[4], brx[4];
#pragma unroll
    for (int im = 0; im < 2; im++) {
        int r = warp_m * 32 + im * 16 + rowsel;
        arb[im] = r * 64; arx[im] = (r >> 1) & 3;
    }
#pragma unroll
    for (int jn = 0; jn < 4; jn++) {
        int r = warp_n * 64 + jn * 16 + rowsel;
        brb[jn] = r * 64; brx[jn] = (r >> 1) & 3;
    }

    float acc[2][8][4];
#pragma unroll
    for (int i = 0; i < 2; i++)
#pragma unroll
        for (int j = 0; j < 8; j++)
#pragma unroll
            for (int q = 0; q < 4; q++) acc[i][j][q] = 0.0f;

    // Prologue: fill stages 0 and 1
    load_chunk(sb,               0,  Ah, Al, sA, nA, Bh, Bl, sB, nB, tid);
    cpa_commit();
    load_chunk(sb + STAGE_BYTES, KC, Ah, Al, sA, nA, Bh, Bl, sB, nB, tid);
    cpa_commit();

    uint32_t aH[2][4], aL[2][4];
    uint32_t bHb[2][4], bLb[2][4];
    uint32_t stg = 0;   // stage index of chunk c

#pragma unroll 1
    for (int c = 0; c < CHUNKS; c++) {
        if (c + 1 < CHUNKS) cpa_wait<1>(); else cpa_wait<0>();
        __syncthreads();   // stage c ready; all warps done computing c-1

        // Prefetch chunk c+2 into the stage freed by chunk c-1 (overlaps MMA)
        if (c + 2 < CHUNKS) {
            uint32_t nstg = stg + STAGE_BYTES;
            if (nstg >= NSTAGE * STAGE_BYTES) nstg = 0;
            uint32_t pstg = nstg + STAGE_BYTES;
            if (pstg >= NSTAGE * STAGE_BYTES) pstg = 0;
            load_chunk(sb + pstg, (c + 2) * KC, Ah, Al, sA, nA, Bh, Bl, sB, nB, tid);
            cpa_commit();
        }

        const uint32_t s = sb + stg;

        // initial fragments: A(kk=0), B(kk=0,jn=0)
#pragma unroll
        for (int im = 0; im < 2; im++) {
            uint32_t off = (uint32_t)arb[im] + (uint32_t)((colsel ^ arx[im]) << 4);
            ldsm4(aH[im], s + AH_OFF + off);
            ldsm4(aL[im], s + AL_OFF + off);
        }
        {
            uint32_t off = (uint32_t)brb[0] + (uint32_t)((colsel ^ brx[0]) << 4);
            ldsm4(bHb[0], s + BH_OFF + off);
            ldsm4(bLb[0], s + BL_OFF + off);
        }

#pragma unroll
        for (int kk = 0; kk < 2; kk++) {
#pragma unroll
            for (int jn = 0; jn < 4; jn++) {
                const int p = (kk * 4 + jn) & 1;
                // Prefetch next B fragments (register double-buffer)
                if (!(kk == 1 && jn == 3)) {
                    const int nk = (jn == 3) ? kk + 1 : kk;
                    const int njn = (jn == 3) ? 0 : jn + 1;
                    uint32_t off = (uint32_t)brb[njn] +
                        (uint32_t)(((nk * 2 + colsel) ^ brx[njn]) << 4);
                    ldsm4(bHb[p ^ 1], s + BH_OFF + off);
                    ldsm4(bLb[p ^ 1], s + BL_OFF + off);
                }
                // 12 MMAs, grouped by pass: same-acc reuse distance = 4
                // pass Ah*Bh
                mma16816(acc[0][2 * jn],     aH[0], bHb[p][0], bHb[p][2]);
                mma16816(acc[0][2 * jn + 1], aH[0], bHb[p][1], bHb[p][3]);
                mma16816(acc[1][2 * jn],     aH[1], bHb[p][0], bHb[p][2]);
                mma16816(acc[1][2 * jn + 1], aH[1], bHb[p][1], bHb[p][3]);
                // pass Ah*Bl
                mma16816(acc[0][2 * jn],     aH[0], bLb[p][0], bLb[p][2]);
                mma16816(acc[0][2 * jn + 1], aH[0], bLb[p][1], bLb[p][3]);
                mma16816(acc[1][2 * jn],     aH[1], bLb[p][0], bLb[p][2]);
                mma16816(acc[1][2 * jn + 1], aH[1], bLb[p][1], bLb[p][3]);
                // pass Al*Bh
                mma16816(acc[0][2 * jn],     aL[0], bHb[p][0], bHb[p][2]);
                mma16816(acc[0][2 * jn + 1], aL[0], bHb[p][1], bHb[p][3]);
                mma16816(acc[1][2 * jn],     aL[1], bHb[p][0], bHb[p][2]);
                mma16816(acc[1][2 * jn + 1], aL[1], bHb[p][1], bHb[p][3]);
                // Reload A fragments for kk=1 after last use in kk=0
                if (jn == 3 && kk == 0) {
#pragma unroll
                    for (int im = 0; im < 2; im++) {
                        uint32_t off = (uint32_t)arb[im] +
                            (uint32_t)(((2 + colsel) ^ arx[im]) << 4);
                        ldsm4(aH[im], s + AH_OFF + off);
                        ldsm4(aL[im], s + AL_OFF + off);
                    }
                }
            }
        }

        stg += STAGE_BYTES;
        if (stg >= NSTAGE * STAGE_BYTES) stg = 0;
    }

    // Epilogue: lane l = 4g+t -> rows g, g+8; cols 2t, 2t+1
    const int g = lane >> 2;
    const int t2 = (lane & 3) * 2;
#pragma unroll
    for (int im = 0; im < 2; im++) {
        int r0 = warp_m * 32 + im * 16 + g;
#pragma unroll
        for (int j = 0; j < 8; j++) {
            int cc = warp_n * 64 + j * 8 + t2;
            float* p0 = Co + (size_t)r0 * sC + cc;
            if (r0 < nrow) {
                if (cc < ncol)     p0[0] = acc[im][j][0];
                if (cc + 1 < ncol) p0[1] = acc[im][j][1];
            }
            if (r0 + 8 < nrow) {
                float* p1 = p0 + 8 * sC;
                if (cc < ncol)     p1[0] = acc[im][j][2];
                if (cc + 1 < ncol) p1[1] = acc[im][j][3];
            }
        }
    }
}

// ---------------------------------------------------------------------------
// GEMM1: scores[b,y,l] = U_w[y,:] . x[b,l,:]  (M=Y, N=L, K=D)
// ---------------------------------------------------------------------------
__global__ __launch_bounds__(256, 2)
void gemm1_tc(float* __restrict__ scores) {
    const int b  = blockIdx.z;
    const int m0 = blockIdx.y * 128;
    const int n0 = blockIdx.x * 128;
    int nA = min(Y - m0, 128);
    int nB = min(L - n0, 128);
    gemm_core<D / KC>(
        g_U_hi + (size_t)m0 * D, g_U_lo + (size_t)m0 * D, D, nA,
        g_x_hi + ((size_t)b * L + n0) * D, g_x_lo + ((size_t)b * L + n0) * D, D, nB,
        scores + ((size_t)b * Y + m0) * L + n0, L, nA, nB);
}

// ---------------------------------------------------------------------------
// GEMM2: m[b,y,d] = alpha[b,y,:] . xT[b,d,:]  (M=Y, N=D, K=LP)
// ---------------------------------------------------------------------------
__global__ __launch_bounds__(256, 2)
void gemm2_tc(float* __restrict__ mout) {
    const int b  = blockIdx.z;
    const int m0 = blockIdx.y * 128;
    const int n0 = blockIdx.x * 128;
    int nA = min(Y - m0, 128);
    gemm_core<LP / KC>(
        g_a_hi + ((size_t)b * Y + m0) * LP, g_a_lo + ((size_t)b * Y + m0) * LP, LP, nA,
        g_xT_hi + ((size_t)b * D + n0) * LP, g_xT_lo + ((size_t)b * D + n0) * LP, LP, 128,
        mout + ((size_t)b * Y + m0) * D + n0, D, nA, 128);
}

// ---------------------------------------------------------------------------
// Splitters / transpose
// ---------------------------------------------------------------------------
__global__ __launch_bounds__(256)
void split_u(const float* __restrict__ src) {
    size_t n = (size_t)Y * D;
    for (size_t i = (size_t)blockIdx.x * 256 + threadIdx.x; i < n; i += (size_t)gridDim.x * 256) {
        float v = src[i];
        __nv_bfloat16 h = __float2bfloat16(v);
        float r = v - __bfloat162float(h);
        g_U_hi[i] = h;
        g_U_lo[i] = __float2bfloat16(r);
    }
}

__global__ __launch_bounds__(256)
void split_x(const float* __restrict__ src) {
    size_t n = (size_t)B * L * D;
    for (size_t i = (size_t)blockIdx.x * 256 + threadIdx.x; i < n; i += (size_t)gridDim.x * 256) {
        float v = src[i];
        __nv_bfloat16 h = __float2bfloat16(v);
        float r = v - __bfloat162float(h);
        g_x_hi[i] = h;
        g_x_lo[i] = __float2bfloat16(r);
    }
}

__global__ __launch_bounds__(256)
void transpose_x(const float* __restrict__ x) {
    __shared__ float t[32][33];
    const int b  = blockIdx.z;
    const int l0 = blockIdx.x * 32;
    const int d0 = blockIdx.y * 32;
    const float* xb = x + (size_t)b * L * D;
    const int tx = threadIdx.x & 31;
    const int ty = threadIdx.x >> 5;   // 0..7
#pragma unroll
    for (int i = ty; i < 32; i += 8) {
        int l = l0 + i;
        t[i][tx] = (l < L) ? xb[(size_t)l * D + d0 + tx] : 0.0f;
    }
    __syncthreads();
#pragma unroll
    for (int i = ty; i < 32; i += 8) {
        int d = d0 + i;
        int l = l0 + tx;
        float v = t[tx][i];
        __nv_bfloat16 h = __float2bfloat16(v);
        float r = v - __bfloat162float(h);
        size_t o = ((size_t)b * D + d) * LP + l;
        g_xT_hi[o] = h;
        g_xT_lo[o] = __float2bfloat16(r);
    }
}

// ---------------------------------------------------------------------------
// Softmax over L per row (in place, fp32) + bf16 hi/lo split output (padded)
// ---------------------------------------------------------------------------
__global__ __launch_bounds__(256)
void softmax_rows(float* __restrict__ a) {
    const int row = blockIdx.x;
    float* p = a + (size_t)row * L;
    const int tid = threadIdx.x;

    float vals[10];
    int cnt = 0;
    float mx = -INFINITY;
    for (int i = tid; i < L; i += 256) {
        float v = p[i];
        vals[cnt++] = v;
        mx = fmaxf(mx, v);
    }
    __shared__ float red[256];
    red[tid] = mx; __syncthreads();
    for (int s = 128; s > 0; s >>= 1) {
        if (tid < s) red[tid] = fmaxf(red[tid], red[tid + s]);
        __syncthreads();
    }
    mx = red[0];
    __syncthreads();

    float sum = 0.f;
    for (int c = 0; c < cnt; c++) {
        vals[c] = expf(vals[c] - mx);
        sum += vals[c];
    }
    red[tid] = sum; __syncthreads();
    for (int s = 128; s > 0; s >>= 1) {
        if (tid < s) red[tid] += red[tid + s];
        __syncthreads();
    }
    float inv = 1.0f / red[0];

    size_t ob = (size_t)row * LP;
    cnt = 0;
    for (int i = tid; i < L; i += 256) {
        float v = vals[cnt++] * inv;
        p[i] = v;
        __nv_bfloat16 h = __float2bfloat16(v);
        float r = v - __bfloat162float(h);
        g_a_hi[ob + i] = h;
        g_a_lo[ob + i] = __float2bfloat16(r);
    }
    __nv_bfloat16 z = __float2bfloat16(0.0f);
    for (int i = L + tid; i < LP; i += 256) {
        g_a_hi[ob + i] = z;
        g_a_lo[ob + i] = z;
    }
}

// ---------------------------------------------------------------------------
// Final dot + BCE term per row; loss reduce
// ---------------------------------------------------------------------------
__global__ __launch_bounds__(128)
void final_kernel(const float* __restrict__ mrr,
                  const float* __restrict__ fw,
                  const float* __restrict__ fb,
                  const float* __restrict__ target,
                  float* __restrict__ out_y) {
    const int r = blockIdx.x;
    const int i = r % Y;
    const float* mp = mrr + (size_t)r * D;
    const float* wp = fw + (size_t)i * D;
    const int tid = threadIdx.x;

    float s = 0.f;
    for (int d = tid; d < D; d += 128) s = fmaf(wp[d], mp[d], s);
#pragma unroll
    for (int off = 16; off > 0; off >>= 1) s += __shfl_down_sync(0xffffffffu, s, off);

    __shared__ float sh[4];
    if ((tid & 31) == 0) sh[tid >> 5] = s;
    __syncthreads();
    if (tid == 0) {
        float yv = sh[0] + sh[1] + sh[2] + sh[3] + fb[i];
        out_y[r] = yv;
        float t = target[r];
        g_bce[r] = fmaxf(yv, 0.f) - yv * t + log1pf(expf(-fabsf(yv)));
    }
}

__global__ __launch_bounds__(256)
void loss_reduce(float* __restrict__ out_loss) {
    __shared__ double sh[256];
    double s = 0.0;
    for (int i = threadIdx.x; i < B * Y; i += 256) s += (double)g_bce[i];
    sh[threadIdx.x] = s;
    __syncthreads();
    for (int st = 128; st > 0; st >>= 1) {
        if (threadIdx.x < st) sh[threadIdx.x] += sh[threadIdx.x + st];
        __syncthreads();
    }
    if (threadIdx.x == 0) out_loss[0] = (float)(sh[0] / (double)(B * Y));
}

// ---------------------------------------------------------------------------
// Launch. Output layout: [y (B*Y), loss (1), alpha (B*Y*L), m (B*Y*D)]
// ---------------------------------------------------------------------------
extern "C" void kernel_launch(void* const* d_in, const int* in_sizes, int n_in,
                              void* d_out, int out_size) {
    const float* x      = (const float*)d_in[0];
    const float* target = (const float*)d_in[1];
    // d_in[2] = text_inputs (unused)
    const float* Uw     = (const float*)d_in[3];
    const float* fw     = (const float*)d_in[4];
    const float* fb     = (const float*)d_in[5];

    float* out       = (float*)d_out;
    float* out_y     = out;
    float* out_loss  = out + (size_t)B * Y;
    float* out_alpha = out_loss + 1;
    float* out_m     = out_alpha + (size_t)B * Y * L;

    cudaFuncSetAttribute(gemm1_tc, cudaFuncAttributeMaxDynamicSharedMemorySize, SMEM_BYTES);
    cudaFuncSetAttribute(gemm2_tc, cudaFuncAttributeMaxDynamicSharedMemorySize, SMEM_BYTES);

    split_u<<<2048, 256>>>(Uw);
    split_x<<<8192, 256>>>(x);
    transpose_x<<<dim3(LP / 32, D / 32, B), 256>>>(x);

    gemm1_tc<<<dim3((L + 127) / 128, (Y + 127) / 128, B), 256, SMEM_BYTES>>>(out_alpha);

    softmax_rows<<<B * Y, 256>>>(out_alpha);

    gemm2_tc<<<dim3(D / 128, (Y + 127) / 128, B), 256, SMEM_BYTES>>>(out_m);

    final_kernel<<<B * Y, 128>>>(out_m, fw, fb, target, out_y);
    loss_reduce<<<1, 256>>>(out_loss);
}

// round 9
// speedup vs baseline: 1.0006x; 1.0006x over previous
#include <cuda_runtime.h>
#include <cuda_bf16.h>
#include <math.h>
#include <stdint.h>

// Problem constants
#define B 8
#define L 2500
#define D 512
#define Y 8921
#define LP 2560            // L padded (K of GEMM2)

// GEMM geometry: CTA tile 128(M) x 128(N), K-chunk 32, 8 warps (32x64 each),
// 2 CTAs per SM (independent barrier domains).
#define KC 32
#define AH_OFF 0
#define AL_OFF 8192
#define BH_OFF 16384
#define BL_OFF 24576
#define STAGE_BYTES 32768            // Ah+Al+Bh+Bl (each 128x32 bf16 = 8KB)
#define NSTAGE 3
#define SMEM_BYTES (NSTAGE * STAGE_BYTES)   // 98304 per CTA; 2 CTAs = 192KB/SM

// ---------------------------------------------------------------------------
// Device scratch (no cudaMalloc allowed)
// ---------------------------------------------------------------------------
__device__ __align__(16) __nv_bfloat16 g_x_hi[(size_t)B * L * D];
__device__ __align__(16) __nv_bfloat16 g_x_lo[(size_t)B * L * D];
__device__ __align__(16) __nv_bfloat16 g_xT_hi[(size_t)B * D * LP];
__device__ __align__(16) __nv_bfloat16 g_xT_lo[(size_t)B * D * LP];
__device__ __align__(16) __nv_bfloat16 g_U_hi[(size_t)Y * D];
__device__ __align__(16) __nv_bfloat16 g_U_lo[(size_t)Y * D];
__device__ __align__(16) __nv_bfloat16 g_a_hi[(size_t)B * Y * LP];
__device__ __align__(16) __nv_bfloat16 g_a_lo[(size_t)B * Y * LP];
__device__ float g_bce[B * Y];

// ---------------------------------------------------------------------------
// PTX helpers (base sm_103-legal)
// ---------------------------------------------------------------------------
__device__ __forceinline__ uint32_t smem_u32(const void* p) {
    uint32_t a;
    asm("{ .reg .u64 t; cvta.to.shared.u64 t, %1; cvt.u32.u64 %0, t; }"
        : "=r"(a) : "l"(p));
    return a;
}
__device__ __forceinline__ void cpa16(uint32_t dst, const void* src, int szbytes) {
    asm volatile("cp.async.cg.shared.global [%0], [%1], 16, %2;"
                 :: "r"(dst), "l"(src), "r"(szbytes) : "memory");
}
__device__ __forceinline__ void cpa_commit() {
    asm volatile("cp.async.commit_group;" ::: "memory");
}
template <int N>
__device__ __forceinline__ void cpa_wait() {
    asm volatile("cp.async.wait_group %0;" :: "n"(N) : "memory");
}
__device__ __forceinline__ void ldsm4(uint32_t* r, uint32_t addr) {
    asm volatile("ldmatrix.sync.aligned.m8n8.x4.shared.b16 {%0,%1,%2,%3}, [%4];"
                 : "=r"(r[0]), "=r"(r[1]), "=r"(r[2]), "=r"(r[3]) : "r"(addr));
}
__device__ __forceinline__ void mma16816(float* c, const uint32_t* a,
                                         uint32_t b0, uint32_t b1) {
    asm volatile(
        "mma.sync.aligned.m16n8k16.row.col.f32.bf16.bf16.f32 "
        "{%0,%1,%2,%3}, {%4,%5,%6,%7}, {%8,%9}, {%0,%1,%2,%3};"
        : "+f"(c[0]), "+f"(c[1]), "+f"(c[2]), "+f"(c[3])
        : "r"(a[0]), "r"(a[1]), "r"(a[2]), "r"(a[3]), "r"(b0), "r"(b1));
}

// 64B-row XOR swizzle: row r, 16B-chunk c (0..3)
__device__ __forceinline__ uint32_t swz64(int r, int c) {
    return (uint32_t)(r * 64 + ((c ^ ((r >> 1) & 3)) << 4));
}

// ---------------------------------------------------------------------------
// Chunk loader: Ah/Al + Bh/Bl, each 128 x 32 bf16, cp.async 16B. 256 threads,
// 8 cp.async per thread.
// ---------------------------------------------------------------------------
__device__ __forceinline__ void load_chunk(uint32_t st, int kt,
        const __nv_bfloat16* __restrict__ Ah, const __nv_bfloat16* __restrict__ Al,
        size_t sA, int nA,
        const __nv_bfloat16* __restrict__ Bh, const __nv_bfloat16* __restrict__ Bl,
        size_t sB, int nB, int tid) {
#pragma unroll
    for (int it = 0; it < 2; it++) {
        int idx = tid + it * 256;
        int r = idx >> 2, c = idx & 3;
        uint32_t o = swz64(r, c);
        bool ok = r < nA;
        size_t so = ok ? ((size_t)r * sA + kt + c * 8) : 0;
        cpa16(st + AH_OFF + o, Ah + so, ok ? 16 : 0);
        cpa16(st + AL_OFF + o, Al + so, ok ? 16 : 0);
    }
#pragma unroll
    for (int it = 0; it < 2; it++) {
        int idx = tid + it * 256;
        int r = idx >> 2, c = idx & 3;
        uint32_t o = swz64(r, c);
        bool ok = r < nB;
        size_t so = ok ? ((size_t)r * sB + kt + c * 8) : 0;
        cpa16(st + BH_OFF + o, Bh + so, ok ? 16 : 0);
        cpa16(st + BL_OFF + o, Bl + so, ok ? 16 : 0);
    }
}

// ---------------------------------------------------------------------------
// Core GEMM: C[m<=128, n<=128] = sum_k (Ah+Al)[m,k]*(Bh+Bl)[n,k] (drop lo*lo)
// 256 threads, 8 warps 4(M) x 2(N), warp tile 32x64, m16n8k16 bf16.
// 3-stage cp.async ring, one barrier per chunk, B-frag register double-buffer.
// MMAs ordered per-pass so same-accumulator reuse distance is 4 (no RAW stall).
// ---------------------------------------------------------------------------
template <int CHUNKS>
__device__ __forceinline__ void gemm_core(
    const __nv_bfloat16* __restrict__ Ah, const __nv_bfloat16* __restrict__ Al,
    size_t sA, int nA,
    const __nv_bfloat16* __restrict__ Bh, const __nv_bfloat16* __restrict__ Bl,
    size_t sB, int nB,
    float* __restrict__ Co, size_t sC, int nrow, int ncol)
{
    extern __shared__ __align__(128) char smem[];
    const uint32_t sb = smem_u32(smem);
    const int tid = threadIdx.x;
    const int lane = tid & 31;
    const int wid = tid >> 5;
    const int warp_m = wid >> 1;     // 0..3 -> 32-row slabs
    const int warp_n = wid & 1;      // 0..1 -> 64-col slabs

    const int rowsel = lane & 15;
    const int colsel = (lane >> 4) & 1;

    // Per-lane row bases and swizzle keys
    int arb[2], arx[2], brb[4], brx[4];
#pragma unroll
    for (int im = 0; im < 2; im++) {
        int r = warp_m * 32 + im * 16 + rowsel;
        arb[im] = r * 64; arx[im] = (r >> 1) & 3;
    }
#pragma unroll
    for (int jn = 0; jn < 4; jn++) {
        int r = warp_n * 64 + jn * 16 + rowsel;
        brb[jn] = r * 64; brx[jn] = (r >> 1) & 3;
    }

    float acc[2][8][4];
#pragma unroll
    for (int i = 0; i < 2; i++)
#pragma unroll
        for (int j = 0; j < 8; j++)
#pragma unroll
            for (int q = 0; q < 4; q++) acc[i][j][q] = 0.0f;

    // Prologue: fill stages 0 and 1
    load_chunk(sb,               0,  Ah, Al, sA, nA, Bh, Bl, sB, nB, tid);
    cpa_commit();
    load_chunk(sb + STAGE_BYTES, KC, Ah, Al, sA, nA, Bh, Bl, sB, nB, tid);
    cpa_commit();

    uint32_t aH[2][4], aL[2][4];
    uint32_t bHb[2][4], bLb[2][4];
    uint32_t stg = 0;   // stage index of chunk c

#pragma unroll 1
    for (int c = 0; c < CHUNKS; c++) {
        if (c + 1 < CHUNKS) cpa_wait<1>(); else cpa_wait<0>();
        __syncthreads();   // stage c ready; all warps done computing c-1

        // Prefetch chunk c+2 into the stage freed by chunk c-1 (overlaps MMA)
        if (c + 2 < CHUNKS) {
            uint32_t nstg = stg + STAGE_BYTES;
            if (nstg >= NSTAGE * STAGE_BYTES) nstg = 0;
            uint32_t pstg = nstg + STAGE_BYTES;
            if (pstg >= NSTAGE * STAGE_BYTES) pstg = 0;
            load_chunk(sb + pstg, (c + 2) * KC, Ah, Al, sA, nA, Bh, Bl, sB, nB, tid);
            cpa_commit();
        }

        const uint32_t s = sb + stg;

        // initial fragments: A(kk=0), B(kk=0,jn=0)
#pragma unroll
        for (int im = 0; im < 2; im++) {
            uint32_t off = (uint32_t)arb[im] + (uint32_t)((colsel ^ arx[im]) << 4);
            ldsm4(aH[im], s + AH_OFF + off);
            ldsm4(aL[im], s + AL_OFF + off);
        }
        {
            uint32_t off = (uint32_t)brb[0] + (uint32_t)((colsel ^ brx[0]) << 4);
            ldsm4(bHb[0], s + BH_OFF + off);
            ldsm4(bLb[0], s + BL_OFF + off);
        }

#pragma unroll
        for (int kk = 0; kk < 2; kk++) {
#pragma unroll
            for (int jn = 0; jn < 4; jn++) {
                const int p = (kk * 4 + jn) & 1;
                // Prefetch next B fragments (register double-buffer)
                if (!(kk == 1 && jn == 3)) {
                    const int nk = (jn == 3) ? kk + 1 : kk;
                    const int njn = (jn == 3) ? 0 : jn + 1;
                    uint32_t off = (uint32_t)brb[njn] +
                        (uint32_t)(((nk * 2 + colsel) ^ brx[njn]) << 4);
                    ldsm4(bHb[p ^ 1], s + BH_OFF + off);
                    ldsm4(bLb[p ^ 1], s + BL_OFF + off);
                }
                // 12 MMAs, grouped by pass: same-acc reuse distance = 4
                // pass Ah*Bh
                mma16816(acc[0][2 * jn],     aH[0], bHb[p][0], bHb[p][2]);
                mma16816(acc[0][2 * jn + 1], aH[0], bHb[p][1], bHb[p][3]);
                mma16816(acc[1][2 * jn],     aH[1], bHb[p][0], bHb[p][2]);
                mma16816(acc[1][2 * jn + 1], aH[1], bHb[p][1], bHb[p][3]);
                // pass Ah*Bl
                mma16816(acc[0][2 * jn],     aH[0], bLb[p][0], bLb[p][2]);
                mma16816(acc[0][2 * jn + 1], aH[0], bLb[p][1], bLb[p][3]);
                mma16816(acc[1][2 * jn],     aH[1], bLb[p][0], bLb[p][2]);
                mma16816(acc[1][2 * jn + 1], aH[1], bLb[p][1], bLb[p][3]);
                // pass Al*Bh
                mma16816(acc[0][2 * jn],     aL[0], bHb[p][0], bHb[p][2]);
                mma16816(acc[0][2 * jn + 1], aL[0], bHb[p][1], bHb[p][3]);
                mma16816(acc[1][2 * jn],     aL[1], bHb[p][0], bHb[p][2]);
                mma16816(acc[1][2 * jn + 1], aL[1], bHb[p][1], bHb[p][3]);
                // Reload A fragments for kk=1 after last use in kk=0
                if (jn == 3 && kk == 0) {
#pragma unroll
                    for (int im = 0; im < 2; im++) {
                        uint32_t off = (uint32_t)arb[im] +
                            (uint32_t)(((2 + colsel) ^ arx[im]) << 4);
                        ldsm4(aH[im], s + AH_OFF + off);
                        ldsm4(aL[im], s + AL_OFF + off);
                    }
                }
            }
        }

        stg += STAGE_BYTES;
        if (stg >= NSTAGE * STAGE_BYTES) stg = 0;
    }

    // Epilogue: lane l = 4g+t -> rows g, g+8; cols 2t, 2t+1
    const int g = lane >> 2;
    const int t2 = (lane & 3) * 2;
#pragma unroll
    for (int im = 0; im < 2; im++) {
        int r0 = warp_m * 32 + im * 16 + g;
#pragma unroll
        for (int j = 0; j < 8; j++) {
            int cc = warp_n * 64 + j * 8 + t2;
            float* p0 = Co + (size_t)r0 * sC + cc;
            if (r0 < nrow) {
                if (cc < ncol)     p0[0] = acc[im][j][0];
                if (cc + 1 < ncol) p0[1] = acc[im][j][1];
            }
            if (r0 + 8 < nrow) {
                float* p1 = p0 + 8 * sC;
                if (cc < ncol)     p1[0] = acc[im][j][2];
                if (cc + 1 < ncol) p1[1] = acc[im][j][3];
            }
        }
    }
}

// ---------------------------------------------------------------------------
// GEMM1: scores[b,y,l] = U_w[y,:] . x[b,l,:]  (M=Y, N=L, K=D)
// ---------------------------------------------------------------------------
__global__ __launch_bounds__(256, 2)
void gemm1_tc(float* __restrict__ scores) {
    const int b  = blockIdx.z;
    const int m0 = blockIdx.y * 128;
    const int n0 = blockIdx.x * 128;
    int nA = min(Y - m0, 128);
    int nB = min(L - n0, 128);
    gemm_core<D / KC>(
        g_U_hi + (size_t)m0 * D, g_U_lo + (size_t)m0 * D, D, nA,
        g_x_hi + ((size_t)b * L + n0) * D, g_x_lo + ((size_t)b * L + n0) * D, D, nB,
        scores + ((size_t)b * Y + m0) * L + n0, L, nA, nB);
}

// ---------------------------------------------------------------------------
// GEMM2: m[b,y,d] = alpha[b,y,:] . xT[b,d,:]  (M=Y, N=D, K=LP)
// ---------------------------------------------------------------------------
__global__ __launch_bounds__(256, 2)
void gemm2_tc(float* __restrict__ mout) {
    const int b  = blockIdx.z;
    const int m0 = blockIdx.y * 128;
    const int n0 = blockIdx.x * 128;
    int nA = min(Y - m0, 128);
    gemm_core<LP / KC>(
        g_a_hi + ((size_t)b * Y + m0) * LP, g_a_lo + ((size_t)b * Y + m0) * LP, LP, nA,
        g_xT_hi + ((size_t)b * D + n0) * LP, g_xT_lo + ((size_t)b * D + n0) * LP, LP, 128,
        mout + ((size_t)b * Y + m0) * D + n0, D, nA, 128);
}

// ---------------------------------------------------------------------------
// Splitters / transpose
// ---------------------------------------------------------------------------
__global__ __launch_bounds__(256)
void split_u(const float* __restrict__ src) {
    size_t n = (size_t)Y * D;
    for (size_t i = (size_t)blockIdx.x * 256 + threadIdx.x; i < n; i += (size_t)gridDim.x * 256) {
        float v = src[i];
        __nv_bfloat16 h = __float2bfloat16(v);
        float r = v - __bfloat162float(h);
        g_U_hi[i] = h;
        g_U_lo[i] = __float2bfloat16(r);
    }
}

__global__ __launch_bounds__(256)
void split_x(const float* __restrict__ src) {
    size_t n = (size_t)B * L * D;
    for (size_t i = (size_t)blockIdx.x * 256 + threadIdx.x; i < n; i += (size_t)gridDim.x * 256) {
        float v = src[i];
        __nv_bfloat16 h = __float2bfloat16(v);
        float r = v - __bfloat162float(h);
        g_x_hi[i] = h;
        g_x_lo[i] = __float2bfloat16(r);
    }
}

__global__ __launch_bounds__(256)
void transpose_x(const float* __restrict__ x) {
    __shared__ float t[32][33];
    const int b  = blockIdx.z;
    const int l0 = blockIdx.x * 32;
    const int d0 = blockIdx.y * 32;
    const float* xb = x + (size_t)b * L * D;
    const int tx = threadIdx.x & 31;
    const int ty = threadIdx.x >> 5;   // 0..7
#pragma unroll
    for (int i = ty; i < 32; i += 8) {
        int l = l0 + i;
        t[i][tx] = (l < L) ? xb[(size_t)l * D + d0 + tx] : 0.0f;
    }
    __syncthreads();
#pragma unroll
    for (int i = ty; i < 32; i += 8) {
        int d = d0 + i;
        int l = l0 + tx;
        float v = t[tx][i];
        __nv_bfloat16 h = __float2bfloat16(v);
        float r = v - __bfloat162float(h);
        size_t o = ((size_t)b * D + d) * LP + l;
        g_xT_hi[o] = h;
        g_xT_lo[o] = __float2bfloat16(r);
    }
}

// ---------------------------------------------------------------------------
// Softmax over L per row (in place, fp32) + bf16 hi/lo split output (padded)
// ---------------------------------------------------------------------------
__global__ __launch_bounds__(256)
void softmax_rows(float* __restrict__ a) {
    const int row = blockIdx.x;
    float* p = a + (size_t)row * L;
    const int tid = threadIdx.x;

    float vals[10];
    int cnt = 0;
    float mx = -INFINITY;
    for (int i = tid; i < L; i += 256) {
        float v = p[i];
        vals[cnt++] = v;
        mx = fmaxf(mx, v);
    }
    __shared__ float red[256];
    red[tid] = mx; __syncthreads();
    for (int s = 128; s > 0; s >>= 1) {
        if (tid < s) red[tid] = fmaxf(red[tid], red[tid + s]);
        __syncthreads();
    }
    mx = red[0];
    __syncthreads();

    float sum = 0.f;
    for (int c = 0; c < cnt; c++) {
        vals[c] = expf(vals[c] - mx);
        sum += vals[c];
    }
    red[tid] = sum; __syncthreads();
    for (int s = 128; s > 0; s >>= 1) {
        if (tid < s) red[tid] += red[tid + s];
        __syncthreads();
    }
    float inv = 1.0f / red[0];

    size_t ob = (size_t)row * LP;
    cnt = 0;
    for (int i = tid; i < L; i += 256) {
        float v = vals[cnt++] * inv;
        p[i] = v;
        __nv_bfloat16 h = __float2bfloat16(v);
        float r = v - __bfloat162float(h);
        g_a_hi[ob + i] = h;
        g_a_lo[ob + i] = __float2bfloat16(r);
    }
    __nv_bfloat16 z = __float2bfloat16(0.0f);
    for (int i = L + tid; i < LP; i += 256) {
        g_a_hi[ob + i] = z;
        g_a_lo[ob + i] = z;
    }
}

// ---------------------------------------------------------------------------
// Final dot + BCE term per row; loss reduce
// ---------------------------------------------------------------------------
__global__ __launch_bounds__(128)
void final_kernel(const float* __restrict__ mrr,
                  const float* __restrict__ fw,
                  const float* __restrict__ fb,
                  const float* __restrict__ target,
                  float* __restrict__ out_y) {
    const int r = blockIdx.x;
    const int i = r % Y;
    const float* mp = mrr + (size_t)r * D;
    const float* wp = fw + (size_t)i * D;
    const int tid = threadIdx.x;

    float s = 0.f;
    for (int d = tid; d < D; d += 128) s = fmaf(wp[d], mp[d], s);
#pragma unroll
    for (int off = 16; off > 0; off >>= 1) s += __shfl_down_sync(0xffffffffu, s, off);

    __shared__ float sh[4];
    if ((tid & 31) == 0) sh[tid >> 5] = s;
    __syncthreads();
    if (tid == 0) {
        float yv = sh[0] + sh[1] + sh[2] + sh[3] + fb[i];
        out_y[r] = yv;
        float t = target[r];
        g_bce[r] = fmaxf(yv, 0.f) - yv * t + log1pf(expf(-fabsf(yv)));
    }
}

__global__ __launch_bounds__(256)
void loss_reduce(float* __restrict__ out_loss) {
    __shared__ double sh[256];
    double s = 0.0;
    for (int i = threadIdx.x; i < B * Y; i += 256) s += (double)g_bce[i];
    sh[threadIdx.x] = s;
    __syncthreads();
    for (int st = 128; st > 0; st >>= 1) {
        if (threadIdx.x < st) sh[threadIdx.x] += sh[threadIdx.x + st];
        __syncthreads();
    }
    if (threadIdx.x == 0) out_loss[0] = (float)(sh[0] / (double)(B * Y));
}

// ---------------------------------------------------------------------------
// Launch. Output layout: [y (B*Y), loss (1), alpha (B*Y*L), m (B*Y*D)]
// ---------------------------------------------------------------------------
extern "C" void kernel_launch(void* const* d_in, const int* in_sizes, int n_in,
                              void* d_out, int out_size) {
    const float* x      = (const float*)d_in[0];
    const float* target = (const float*)d_in[1];
    // d_in[2] = text_inputs (unused)
    const float* Uw     = (const float*)d_in[3];
    const float* fw     = (const float*)d_in[4];
    const float* fb     = (const float*)d_in[5];

    float* out       = (float*)d_out;
    float* out_y     = out;
    float* out_loss  = out + (size_t)B * Y;
    float* out_alpha = out_loss + 1;
    float* out_m     = out_alpha + (size_t)B * Y * L;

    cudaFuncSetAttribute(gemm1_tc, cudaFuncAttributeMaxDynamicSharedMemorySize, SMEM_BYTES);
    cudaFuncSetAttribute(gemm2_tc, cudaFuncAttributeMaxDynamicSharedMemorySize, SMEM_BYTES);

    split_u<<<2048, 256>>>(Uw);
    split_x<<<8192, 256>>>(x);
    transpose_x<<<dim3(LP / 32, D / 32, B), 256>>>(x);

    gemm1_tc<<<dim3((L + 127) / 128, (Y + 127) / 128, B), 256, SMEM_BYTES>>>(out_alpha);

    softmax_rows<<<B * Y, 256>>>(out_alpha);

    gemm2_tc<<<dim3(D / 128, (Y + 127) / 128, B), 256, SMEM_BYTES>>>(out_m);

    final_kernel<<<B * Y, 128>>>(out_m, fw, fb, target, out_y);
    loss_reduce<<<1, 256>>>(out_loss);
}

// round 10
// speedup vs baseline: 1.0870x; 1.0863x over previous
#include <cuda_runtime.h>
#include <cuda_bf16.h>
#include <math.h>
#include <stdint.h>

// Problem constants
#define B 8
#define L 2500
#define D 512
#define Y 8921
#define LP 2560            // L padded (K of GEMM2)

// GEMM geometry: CTA tile 128(M) x 128(N), K-chunk 32, 8 warps (32x64 each),
// 2 CTAs per SM.
#define KC 32
#define AH_OFF 0
#define AL_OFF 8192
#define BH_OFF 16384
#define BL_OFF 24576
#define STAGE_BYTES 32768            // Ah+Al+Bh+Bl (each 128x32 bf16 = 8KB)
#define NSTAGE 3
#define SMEM_BYTES (NSTAGE * STAGE_BYTES)   // 98304/CTA; 2 CTAs = 192KB/SM

// ---------------------------------------------------------------------------
// Device scratch: merged hi/lo arrays (lo at compile-time element offset)
// ---------------------------------------------------------------------------
#define XOFFE  ((size_t)B * L * D)
#define XTOFFE ((size_t)B * D * LP)
#define UOFFE  ((size_t)Y * D)
#define AOFFE2 ((size_t)B * Y * LP)

__device__ __align__(16) __nv_bfloat16 g_x2[2 * XOFFE];
__device__ __align__(16) __nv_bfloat16 g_xT2[2 * XTOFFE];
__device__ __align__(16) __nv_bfloat16 g_U2[2 * UOFFE];
__device__ __align__(16) __nv_bfloat16 g_a2[2 * AOFFE2];
__device__ float g_bce[B * Y];

// ---------------------------------------------------------------------------
// PTX helpers (base sm_103-legal)
// ---------------------------------------------------------------------------
__device__ __forceinline__ uint32_t smem_u32(const void* p) {
    uint32_t a;
    asm("{ .reg .u64 t; cvta.to.shared.u64 t, %1; cvt.u32.u64 %0, t; }"
        : "=r"(a) : "l"(p));
    return a;
}
__device__ __forceinline__ void cpa16(uint32_t dst, const void* src, int szbytes) {
    asm volatile("cp.async.cg.shared.global [%0], [%1], 16, %2;"
                 :: "r"(dst), "l"(src), "r"(szbytes) : "memory");
}
__device__ __forceinline__ void cpa_commit() {
    asm volatile("cp.async.commit_group;" ::: "memory");
}
template <int N>
__device__ __forceinline__ void cpa_wait() {
    asm volatile("cp.async.wait_group %0;" :: "n"(N) : "memory");
}
__device__ __forceinline__ void ldsm4(uint32_t* r, uint32_t addr) {
    asm volatile("ldmatrix.sync.aligned.m8n8.x4.shared.b16 {%0,%1,%2,%3}, [%4];"
                 : "=r"(r[0]), "=r"(r[1]), "=r"(r[2]), "=r"(r[3]) : "r"(addr));
}
__device__ __forceinline__ void mma16816(float* c, const uint32_t* a,
                                         uint32_t b0, uint32_t b1) {
    asm volatile(
        "mma.sync.aligned.m16n8k16.row.col.f32.bf16.bf16.f32 "
        "{%0,%1,%2,%3}, {%4,%5,%6,%7}, {%8,%9}, {%0,%1,%2,%3};"
        : "+f"(c[0]), "+f"(c[1]), "+f"(c[2]), "+f"(c[3])
        : "r"(a[0]), "r"(a[1]), "r"(a[2]), "r"(a[3]), "r"(b0), "r"(b1));
}

// 64B-row XOR swizzle: row r, 16B-chunk c (0..3)
__device__ __forceinline__ uint32_t swz64(int r, int c) {
    return (uint32_t)(r * 64 + ((c ^ ((r >> 1) & 3)) << 4));
}

// ---------------------------------------------------------------------------
// Core GEMM: C[m<=128, n<=128] = sum_k (Ah+Al)[m,k]*(Bh+Bl)[n,k] (drop lo*lo)
// 256 threads, 8 warps 4(M) x 2(N), warp tile 32x64, m16n8k16 bf16.
// Compile-time strides; merged hi/lo operands; cp.async interleaved into MMAs.
// ---------------------------------------------------------------------------
template <int CHUNKS, int SA, int SB, size_t AOFFE, size_t BOFFE>
__device__ __forceinline__ void gemm_core(
    const __nv_bfloat16* __restrict__ Ahi, int nA,
    const __nv_bfloat16* __restrict__ Bhi, int nB,
    float* __restrict__ Co, int sC, int nrow, int ncol)
{
    extern __shared__ __align__(128) char smem[];
    const uint32_t sb = smem_u32(smem);
    const int tid = threadIdx.x;
    const int lane = tid & 31;
    const int wid = tid >> 5;
    const int warp_m = wid >> 1;     // 0..3 -> 32-row slabs
    const int warp_n = wid & 1;      // 0..1 -> 64-col slabs
    const int rowsel = lane & 15;
    const int colsel = (lane >> 4) & 1;

    // ---- cp.async per-thread state (all strides compile-time)
    const int rT = tid >> 2, cT = tid & 3;
    const uint32_t so0 = swz64(rT, cT);
    const uint32_t so1 = swz64(rT + 64, cT);
    const __nv_bfloat16* pA = Ahi + (size_t)rT * SA + cT * 8;
    const __nv_bfloat16* pB = Bhi + (size_t)rT * SB + cT * 8;
    const int szA0 = (rT < nA) ? 16 : 0;
    const int szA1 = (rT + 64 < nA) ? 16 : 0;
    const int szB0 = (rT < nB) ? 16 : 0;
    const int szB1 = (rT + 64 < nB) ? 16 : 0;

    auto load_a = [&](uint32_t st) {
        cpa16(st + (AH_OFF) + so0, pA, szA0);
        cpa16(st + (AL_OFF) + so0, pA + AOFFE, szA0);
        cpa16(st + (AH_OFF) + so1, pA + (size_t)64 * SA, szA1);
        cpa16(st + (AL_OFF) + so1, pA + (size_t)64 * SA + AOFFE, szA1);
        pA += KC;
    };
    auto load_b = [&](uint32_t st) {
        cpa16(st + (BH_OFF) + so0, pB, szB0);
        cpa16(st + (BL_OFF) + so0, pB + BOFFE, szB0);
        cpa16(st + (BH_OFF) + so1, pB + (size_t)64 * SB, szB1);
        cpa16(st + (BL_OFF) + so1, pB + (size_t)64 * SB + BOFFE, szB1);
        pB += KC;
    };

    // ---- precomputed LDSM offsets (within stage, hi planes; lo = +8192)
    uint32_t offA[2][2];   // [kk][im]
#pragma unroll
    for (int im = 0; im < 2; im++) {
        int r = warp_m * 32 + im * 16 + rowsel;
#pragma unroll
        for (int kk = 0; kk < 2; kk++)
            offA[kk][im] = (uint32_t)(AH_OFF + r * 64 +
                           (((kk * 2 + colsel) ^ ((r >> 1) & 3)) << 4));
    }
    uint32_t offB[2][4];   // [kk][jn]
#pragma unroll
    for (int jn = 0; jn < 4; jn++) {
        int r = warp_n * 64 + jn * 16 + rowsel;
#pragma unroll
        for (int kk = 0; kk < 2; kk++)
            offB[kk][jn] = (uint32_t)(BH_OFF + r * 64 +
                           (((kk * 2 + colsel) ^ ((r >> 1) & 3)) << 4));
    }

    float acc[2][8][4];
#pragma unroll
    for (int i = 0; i < 2; i++)
#pragma unroll
        for (int j = 0; j < 8; j++)
#pragma unroll
            for (int q = 0; q < 4; q++) acc[i][j][q] = 0.0f;

    // Prologue: fill stages 0 and 1
    load_a(sb); load_b(sb); cpa_commit();
    load_a(sb + STAGE_BYTES); load_b(sb + STAGE_BYTES); cpa_commit();

    uint32_t aH[2][4], aL[2][4];
    uint32_t bHb[2][4], bLb[2][4];
    uint32_t stg = 0;

#pragma unroll 1
    for (int c = 0; c < CHUNKS; c++) {
        if (c + 1 < CHUNKS) cpa_wait<1>(); else cpa_wait<0>();
        __syncthreads();   // stage c ready; all warps done computing c-1

        const uint32_t s = sb + stg;
        uint32_t pstg = stg + 2 * STAGE_BYTES;
        if (pstg >= NSTAGE * STAGE_BYTES) pstg -= NSTAGE * STAGE_BYTES;
        const uint32_t pf = sb + pstg;
        const bool do_pf = (c + 2 < CHUNKS);

        // initial fragments: A(kk=0), B(kk=0,jn=0)
#pragma unroll
        for (int im = 0; im < 2; im++) {
            uint32_t a0 = s + offA[0][im];
            ldsm4(aH[im], a0);
            ldsm4(aL[im], a0 + 8192);
        }
        {
            uint32_t b0 = s + offB[0][0];
            ldsm4(bHb[0], b0);
            ldsm4(bLb[0], b0 + 8192);
        }

#pragma unroll
        for (int kk = 0; kk < 2; kk++) {
#pragma unroll
            for (int jn = 0; jn < 4; jn++) {
                const int p = (kk * 4 + jn) & 1;
                // Prefetch next B fragments (register double-buffer)
                if (!(kk == 1 && jn == 3)) {
                    const int nk = (jn == 3) ? kk + 1 : kk;
                    const int njn = (jn == 3) ? 0 : jn + 1;
                    uint32_t b0 = s + offB[nk][njn];
                    ldsm4(bHb[p ^ 1], b0);
                    ldsm4(bLb[p ^ 1], b0 + 8192);
                }
                // 12 MMAs (pass-grouped)
                mma16816(acc[0][2 * jn],     aH[0], bHb[p][0], bHb[p][2]);
                mma16816(acc[0][2 * jn + 1], aH[0], bHb[p][1], bHb[p][3]);
                mma16816(acc[1][2 * jn],     aH[1], bHb[p][0], bHb[p][2]);
                mma16816(acc[1][2 * jn + 1], aH[1], bHb[p][1], bHb[p][3]);
                mma16816(acc[0][2 * jn],     aH[0], bLb[p][0], bLb[p][2]);
                mma16816(acc[0][2 * jn + 1], aH[0], bLb[p][1], bLb[p][3]);
                mma16816(acc[1][2 * jn],     aH[1], bLb[p][0], bLb[p][2]);
                mma16816(acc[1][2 * jn + 1], aH[1], bLb[p][1], bLb[p][3]);
                mma16816(acc[0][2 * jn],     aL[0], bHb[p][0], bHb[p][2]);
                mma16816(acc[0][2 * jn + 1], aL[0], bHb[p][1], bHb[p][3]);
                mma16816(acc[1][2 * jn],     aL[1], bHb[p][0], bHb[p][2]);
                mma16816(acc[1][2 * jn + 1], aL[1], bHb[p][1], bHb[p][3]);
                // Interleaved gmem prefetch for chunk c+2 (after MMAs issued)
                if (kk == 0 && jn == 1 && do_pf) load_a(pf);
                if (kk == 0 && jn == 2 && do_pf) { load_b(pf); cpa_commit(); }
                // Reload A fragments for kk=1 after last use in kk=0
                if (jn == 3 && kk == 0) {
#pragma unroll
                    for (int im = 0; im < 2; im++) {
                        uint32_t a0 = s + offA[1][im];
                        ldsm4(aH[im], a0);
                        ldsm4(aL[im], a0 + 8192);
                    }
                }
            }
        }

        stg += STAGE_BYTES;
        if (stg >= NSTAGE * STAGE_BYTES) stg = 0;
    }

    // Epilogue: lane l = 4g+t -> rows g, g+8; cols 2t, 2t+1
    const int g = lane >> 2;
    const int t2 = (lane & 3) * 2;
#pragma unroll
    for (int im = 0; im < 2; im++) {
        int r0 = warp_m * 32 + im * 16 + g;
#pragma unroll
        for (int j = 0; j < 8; j++) {
            int cc = warp_n * 64 + j * 8 + t2;
            float* p0 = Co + (size_t)r0 * sC + cc;
            if (r0 < nrow) {
                if (cc < ncol)     p0[0] = acc[im][j][0];
                if (cc + 1 < ncol) p0[1] = acc[im][j][1];
            }
            if (r0 + 8 < nrow) {
                float* p1 = p0 + 8 * sC;
                if (cc < ncol)     p1[0] = acc[im][j][2];
                if (cc + 1 < ncol) p1[1] = acc[im][j][3];
            }
        }
    }
}

// ---------------------------------------------------------------------------
// GEMM1: scores[b,y,l] = U_w[y,:] . x[b,l,:]  (M=Y, N=L, K=D)
// ---------------------------------------------------------------------------
__global__ __launch_bounds__(256, 2)
void gemm1_tc(float* __restrict__ scores) {
    const int b  = blockIdx.z;
    const int m0 = blockIdx.y * 128;
    const int n0 = blockIdx.x * 128;
    int nA = min(Y - m0, 128);
    int nB = min(L - n0, 128);
    gemm_core<D / KC, D, D, UOFFE, XOFFE>(
        g_U2 + (size_t)m0 * D, nA,
        g_x2 + ((size_t)b * L + n0) * D, nB,
        scores + ((size_t)b * Y + m0) * L + n0, L, nA, nB);
}

// ---------------------------------------------------------------------------
// GEMM2: m[b,y,d] = alpha[b,y,:] . xT[b,d,:]  (M=Y, N=D, K=LP)
// ---------------------------------------------------------------------------
__global__ __launch_bounds__(256, 2)
void gemm2_tc(float* __restrict__ mout) {
    const int b  = blockIdx.z;
    const int m0 = blockIdx.y * 128;
    const int n0 = blockIdx.x * 128;
    int nA = min(Y - m0, 128);
    gemm_core<LP / KC, LP, LP, AOFFE2, XTOFFE>(
        g_a2 + ((size_t)b * Y + m0) * LP, nA,
        g_xT2 + ((size_t)b * D + n0) * LP, 128,
        mout + ((size_t)b * Y + m0) * D + n0, D, nA, 128);
}

// ---------------------------------------------------------------------------
// Splitters / transpose (merged hi/lo arrays)
// ---------------------------------------------------------------------------
__global__ __launch_bounds__(256)
void split_u(const float* __restrict__ src) {
    size_t n = UOFFE;
    for (size_t i = (size_t)blockIdx.x * 256 + threadIdx.x; i < n; i += (size_t)gridDim.x * 256) {
        float v = src[i];
        __nv_bfloat16 h = __float2bfloat16(v);
        float r = v - __bfloat162float(h);
        g_U2[i] = h;
        g_U2[i + UOFFE] = __float2bfloat16(r);
    }
}

__global__ __launch_bounds__(256)
void split_x(const float* __restrict__ src) {
    size_t n = XOFFE;
    for (size_t i = (size_t)blockIdx.x * 256 + threadIdx.x; i < n; i += (size_t)gridDim.x * 256) {
        float v = src[i];
        __nv_bfloat16 h = __float2bfloat16(v);
        float r = v - __bfloat162float(h);
        g_x2[i] = h;
        g_x2[i + XOFFE] = __float2bfloat16(r);
    }
}

__global__ __launch_bounds__(256)
void transpose_x(const float* __restrict__ x) {
    __shared__ float t[32][33];
    const int b  = blockIdx.z;
    const int l0 = blockIdx.x * 32;
    const int d0 = blockIdx.y * 32;
    const float* xb = x + (size_t)b * L * D;
    const int tx = threadIdx.x & 31;
    const int ty = threadIdx.x >> 5;   // 0..7
#pragma unroll
    for (int i = ty; i < 32; i += 8) {
        int l = l0 + i;
        t[i][tx] = (l < L) ? xb[(size_t)l * D + d0 + tx] : 0.0f;
    }
    __syncthreads();
#pragma unroll
    for (int i = ty; i < 32; i += 8) {
        int d = d0 + i;
        int l = l0 + tx;
        float v = t[tx][i];
        __nv_bfloat16 h = __float2bfloat16(v);
        float r = v - __bfloat162float(h);
        size_t o = ((size_t)b * D + d) * LP + l;
        g_xT2[o] = h;
        g_xT2[o + XTOFFE] = __float2bfloat16(r);
    }
}

// ---------------------------------------------------------------------------
// Softmax over L per row (in place, fp32) + bf16 hi/lo split output (padded)
// ---------------------------------------------------------------------------
__global__ __launch_bounds__(256)
void softmax_rows(float* __restrict__ a) {
    const int row = blockIdx.x;
    float* p = a + (size_t)row * L;
    const int tid = threadIdx.x;

    float vals[10];
    int cnt = 0;
    float mx = -INFINITY;
    for (int i = tid; i < L; i += 256) {
        float v = p[i];
        vals[cnt++] = v;
        mx = fmaxf(mx, v);
    }
    __shared__ float red[256];
    red[tid] = mx; __syncthreads();
    for (int s = 128; s > 0; s >>= 1) {
        if (tid < s) red[tid] = fmaxf(red[tid], red[tid + s]);
        __syncthreads();
    }
    mx = red[0];
    __syncthreads();

    float sum = 0.f;
    for (int c = 0; c < cnt; c++) {
        vals[c] = expf(vals[c] - mx);
        sum += vals[c];
    }
    red[tid] = sum; __syncthreads();
    for (int s = 128; s > 0; s >>= 1) {
        if (tid < s) red[tid] += red[tid + s];
        __syncthreads();
    }
    float inv = 1.0f / red[0];

    size_t ob = (size_t)row * LP;
    cnt = 0;
    for (int i = tid; i < L; i += 256) {
        float v = vals[cnt++] * inv;
        p[i] = v;
        __nv_bfloat16 h = __float2bfloat16(v);
        float r = v - __bfloat162float(h);
        g_a2[ob + i] = h;
        g_a2[ob + i + AOFFE2] = __float2bfloat16(r);
    }
    __nv_bfloat16 z = __float2bfloat16(0.0f);
    for (int i = L + tid; i < LP; i += 256) {
        g_a2[ob + i] = z;
        g_a2[ob + i + AOFFE2] = z;
    }
}

// ---------------------------------------------------------------------------
// Final dot + BCE term per row; loss reduce
// ---------------------------------------------------------------------------
__global__ __launch_bounds__(128)
void final_kernel(const float* __restrict__ mrr,
                  const float* __restrict__ fw,
                  const float* __restrict__ fb,
                  const float* __restrict__ target,
                  float* __restrict__ out_y) {
    const int r = blockIdx.x;
    const int i = r % Y;
    const float* mp = mrr + (size_t)r * D;
    const float* wp = fw + (size_t)i * D;
    const int tid = threadIdx.x;

    float s = 0.f;
    for (int d = tid; d < D; d += 128) s = fmaf(wp[d], mp[d], s);
#pragma unroll
    for (int off = 16; off > 0; off >>= 1) s += __shfl_down_sync(0xffffffffu, s, off);

    __shared__ float sh[4];
    if ((tid & 31) == 0) sh[tid >> 5] = s;
    __syncthreads();
    if (tid == 0) {
        float yv = sh[0] + sh[1] + sh[2] + sh[3] + fb[i];
        out_y[r] = yv;
        float t = target[r];
        g_bce[r] = fmaxf(yv, 0.f) - yv * t + log1pf(expf(-fabsf(yv)));
    }
}

__global__ __launch_bounds__(256)
void loss_reduce(float* __restrict__ out_loss) {
    __shared__ double sh[256];
    double s = 0.0;
    for (int i = threadIdx.x; i < B * Y; i += 256) s += (double)g_bce[i];
    sh[threadIdx.x] = s;
    __syncthreads();
    for (int st = 128; st > 0; st >>= 1) {
        if (threadIdx.x < st) sh[threadIdx.x] += sh[threadIdx.x + st];
        __syncthreads();
    }
    if (threadIdx.x == 0) out_loss[0] = (float)(sh[0] / (double)(B * Y));
}

// ---------------------------------------------------------------------------
// Launch. Output layout: [y (B*Y), loss (1), alpha (B*Y*L), m (B*Y*D)]
// ---------------------------------------------------------------------------
extern "C" void kernel_launch(void* const* d_in, const int* in_sizes, int n_in,
                              void* d_out, int out_size) {
    const float* x      = (const float*)d_in[0];
    const float* target = (const float*)d_in[1];
    // d_in[2] = text_inputs (unused)
    const float* Uw     = (const float*)d_in[3];
    const float* fw     = (const float*)d_in[4];
    const float* fb     = (const float*)d_in[5];

    float* out       = (float*)d_out;
    float* out_y     = out;
    float* out_loss  = out + (size_t)B * Y;
    float* out_alpha = out_loss + 1;
    float* out_m     = out_alpha + (size_t)B * Y * L;

    cudaFuncSetAttribute(gemm1_tc, cudaFuncAttributeMaxDynamicSharedMemorySize, SMEM_BYTES);
    cudaFuncSetAttribute(gemm2_tc, cudaFuncAttributeMaxDynamicSharedMemorySize, SMEM_BYTES);

    split_u<<<2048, 256>>>(Uw);
    split_x<<<8192, 256>>>(x);
    transpose_x<<<dim3(LP / 32, D / 32, B), 256>>>(x);

    gemm1_tc<<<dim3((L + 127) / 128, (Y + 127) / 128, B), 256, SMEM_BYTES>>>(out_alpha);

    softmax_rows<<<B * Y, 256>>>(out_alpha);

    gemm2_tc<<<dim3(D / 128, (Y + 127) / 128, B), 256, SMEM_BYTES>>>(out_m);

    final_kernel<<<B * Y, 128>>>(out_m, fw, fb, target, out_y);
    loss_reduce<<<1, 256>>>(out_loss);
}

// round 11
// speedup vs baseline: 1.4563x; 1.3398x over previous
#include <cuda_runtime.h>
#include <cuda_fp16.h>
#include <math.h>
#include <stdint.h>

// Problem constants
#define B 8
#define L 2500
#define D 512
#define Y 8921
#define LP 2560            // L padded (K of GEMM2)

// GEMM geometry: CTA tile 128(M) x 128(N), K-chunk 32, 8 warps (32x64 each),
// 2 CTAs per SM. fp16 2-pass error split: C = Ah*Bh + Al*Bh.
#define KC 32
#define AH_OFF 0
#define AL_OFF 8192
#define BH_OFF 16384
#define STAGE_BYTES 24576            // Ah+Al+Bh (each 128x32 fp16 = 8KB)
#define NSTAGE 3
#define SMEM_BYTES (NSTAGE * STAGE_BYTES)   // 73728/CTA; 2 CTAs = 144KB/SM

// ---------------------------------------------------------------------------
// Device scratch: A-side merged hi/lo; B-side hi only
// ---------------------------------------------------------------------------
#define XOFFE  ((size_t)B * L * D)
#define XTOFFE ((size_t)B * D * LP)
#define UOFFE  ((size_t)Y * D)
#define AOFFE2 ((size_t)B * Y * LP)

__device__ __align__(16) __half g_x2[XOFFE];        // hi only
__device__ __align__(16) __half g_xT2[XTOFFE];      // hi only
__device__ __align__(16) __half g_U2[2 * UOFFE];    // hi + lo
__device__ __align__(16) __half g_a2[2 * AOFFE2];   // hi + lo
__device__ float g_bce[B * Y];

// ---------------------------------------------------------------------------
// PTX helpers (base sm_103-legal)
// ---------------------------------------------------------------------------
__device__ __forceinline__ uint32_t smem_u32(const void* p) {
    uint32_t a;
    asm("{ .reg .u64 t; cvta.to.shared.u64 t, %1; cvt.u32.u64 %0, t; }"
        : "=r"(a) : "l"(p));
    return a;
}
__device__ __forceinline__ void cpa16(uint32_t dst, const void* src, int szbytes) {
    asm volatile("cp.async.cg.shared.global [%0], [%1], 16, %2;"
                 :: "r"(dst), "l"(src), "r"(szbytes) : "memory");
}
__device__ __forceinline__ void cpa_commit() {
    asm volatile("cp.async.commit_group;" ::: "memory");
}
template <int N>
__device__ __forceinline__ void cpa_wait() {
    asm volatile("cp.async.wait_group %0;" :: "n"(N) : "memory");
}
__device__ __forceinline__ void ldsm4(uint32_t* r, uint32_t addr) {
    asm volatile("ldmatrix.sync.aligned.m8n8.x4.shared.b16 {%0,%1,%2,%3}, [%4];"
                 : "=r"(r[0]), "=r"(r[1]), "=r"(r[2]), "=r"(r[3]) : "r"(addr));
}
__device__ __forceinline__ void mma16816(float* c, const uint32_t* a,
                                         uint32_t b0, uint32_t b1) {
    asm volatile(
        "mma.sync.aligned.m16n8k16.row.col.f32.f16.f16.f32 "
        "{%0,%1,%2,%3}, {%4,%5,%6,%7}, {%8,%9}, {%0,%1,%2,%3};"
        : "+f"(c[0]), "+f"(c[1]), "+f"(c[2]), "+f"(c[3])
        : "r"(a[0]), "r"(a[1]), "r"(a[2]), "r"(a[3]), "r"(b0), "r"(b1));
}

// 64B-row XOR swizzle: row r, 16B-chunk c (0..3)
__device__ __forceinline__ uint32_t swz64(int r, int c) {
    return (uint32_t)(r * 64 + ((c ^ ((r >> 1) & 3)) << 4));
}

// ---------------------------------------------------------------------------
// Core GEMM: C[m<=128, n<=128] = sum_k Ah[m,k]*Bh[n,k] + Al[m,k]*Bh[n,k]
// 256 threads, 8 warps 4(M) x 2(N), warp tile 32x64, m16n8k16 fp16.
// Compile-time strides; cp.async interleaved into the MMA stream.
// ---------------------------------------------------------------------------
template <int CHUNKS, int SA, int SB, size_t AOFFE>
__device__ __forceinline__ void gemm_core(
    const __half* __restrict__ Ahi, int nA,
    const __half* __restrict__ Bhi, int nB,
    float* __restrict__ Co, int sC, int nrow, int ncol)
{
    extern __shared__ __align__(128) char smem[];
    const uint32_t sb = smem_u32(smem);
    const int tid = threadIdx.x;
    const int lane = tid & 31;
    const int wid = tid >> 5;
    const int warp_m = wid >> 1;     // 0..3 -> 32-row slabs
    const int warp_n = wid & 1;      // 0..1 -> 64-col slabs
    const int rowsel = lane & 15;
    const int colsel = (lane >> 4) & 1;

    // ---- cp.async per-thread state (compile-time strides)
    const int rT = tid >> 2, cT = tid & 3;
    const uint32_t so0 = swz64(rT, cT);
    const uint32_t so1 = swz64(rT + 64, cT);
    const __half* pA = Ahi + (size_t)rT * SA + cT * 8;
    const __half* pB = Bhi + (size_t)rT * SB + cT * 8;
    const int szA0 = (rT < nA) ? 16 : 0;
    const int szA1 = (rT + 64 < nA) ? 16 : 0;
    const int szB0 = (rT < nB) ? 16 : 0;
    const int szB1 = (rT + 64 < nB) ? 16 : 0;

    auto load_a = [&](uint32_t st) {
        cpa16(st + AH_OFF + so0, pA, szA0);
        cpa16(st + AL_OFF + so0, pA + AOFFE, szA0);
        cpa16(st + AH_OFF + so1, pA + (size_t)64 * SA, szA1);
        cpa16(st + AL_OFF + so1, pA + (size_t)64 * SA + AOFFE, szA1);
        pA += KC;
    };
    auto load_b = [&](uint32_t st) {
        cpa16(st + BH_OFF + so0, pB, szB0);
        cpa16(st + BH_OFF + so1, pB + (size_t)64 * SB, szB1);
        pB += KC;
    };

    // ---- precomputed LDSM offsets (A hi plane; lo = +8192)
    uint32_t offA[2][2];   // [kk][im]
#pragma unroll
    for (int im = 0; im < 2; im++) {
        int r = warp_m * 32 + im * 16 + rowsel;
#pragma unroll
        for (int kk = 0; kk < 2; kk++)
            offA[kk][im] = (uint32_t)(AH_OFF + r * 64 +
                           (((kk * 2 + colsel) ^ ((r >> 1) & 3)) << 4));
    }
    uint32_t offB[2][4];   // [kk][jn]
#pragma unroll
    for (int jn = 0; jn < 4; jn++) {
        int r = warp_n * 64 + jn * 16 + rowsel;
#pragma unroll
        for (int kk = 0; kk < 2; kk++)
            offB[kk][jn] = (uint32_t)(BH_OFF + r * 64 +
                           (((kk * 2 + colsel) ^ ((r >> 1) & 3)) << 4));
    }

    float acc[2][8][4];
#pragma unroll
    for (int i = 0; i < 2; i++)
#pragma unroll
        for (int j = 0; j < 8; j++)
#pragma unroll
            for (int q = 0; q < 4; q++) acc[i][j][q] = 0.0f;

    // Prologue: fill stages 0 and 1
    load_a(sb); load_b(sb); cpa_commit();
    load_a(sb + STAGE_BYTES); load_b(sb + STAGE_BYTES); cpa_commit();

    uint32_t aH[2][4], aL[2][4];
    uint32_t bHb[2][4];
    uint32_t stg = 0;

#pragma unroll 1
    for (int c = 0; c < CHUNKS; c++) {
        if (c + 1 < CHUNKS) cpa_wait<1>(); else cpa_wait<0>();
        __syncthreads();   // stage c ready; all warps done computing c-1

        const uint32_t s = sb + stg;
        uint32_t pstg = stg + 2 * STAGE_BYTES;
        if (pstg >= NSTAGE * STAGE_BYTES) pstg -= NSTAGE * STAGE_BYTES;
        const uint32_t pf = sb + pstg;
        const bool do_pf = (c + 2 < CHUNKS);

        // initial fragments: A(kk=0), B(kk=0,jn=0)
#pragma unroll
        for (int im = 0; im < 2; im++) {
            uint32_t a0 = s + offA[0][im];
            ldsm4(aH[im], a0);
            ldsm4(aL[im], a0 + 8192);
        }
        ldsm4(bHb[0], s + offB[0][0]);

#pragma unroll
        for (int kk = 0; kk < 2; kk++) {
#pragma unroll
            for (int jn = 0; jn < 4; jn++) {
                const int p = (kk * 4 + jn) & 1;
                // Prefetch next B fragment (register double-buffer)
                if (!(kk == 1 && jn == 3)) {
                    const int nk = (jn == 3) ? kk + 1 : kk;
                    const int njn = (jn == 3) ? 0 : jn + 1;
                    ldsm4(bHb[p ^ 1], s + offB[nk][njn]);
                }
                // 8 MMAs: pass Ah*Bh then Al*Bh
                mma16816(acc[0][2 * jn],     aH[0], bHb[p][0], bHb[p][2]);
                mma16816(acc[0][2 * jn + 1], aH[0], bHb[p][1], bHb[p][3]);
                mma16816(acc[1][2 * jn],     aH[1], bHb[p][0], bHb[p][2]);
                mma16816(acc[1][2 * jn + 1], aH[1], bHb[p][1], bHb[p][3]);
                mma16816(acc[0][2 * jn],     aL[0], bHb[p][0], bHb[p][2]);
                mma16816(acc[0][2 * jn + 1], aL[0], bHb[p][1], bHb[p][3]);
                mma16816(acc[1][2 * jn],     aL[1], bHb[p][0], bHb[p][2]);
                mma16816(acc[1][2 * jn + 1], aL[1], bHb[p][1], bHb[p][3]);
                // Interleaved gmem prefetch for chunk c+2
                if (kk == 0 && jn == 1 && do_pf) load_a(pf);
                if (kk == 0 && jn == 2 && do_pf) { load_b(pf); cpa_commit(); }
                // Reload A fragments for kk=1 after last use in kk=0
                if (jn == 3 && kk == 0) {
#pragma unroll
                    for (int im = 0; im < 2; im++) {
                        uint32_t a0 = s + offA[1][im];
                        ldsm4(aH[im], a0);
                        ldsm4(aL[im], a0 + 8192);
                    }
                }
            }
        }

        stg += STAGE_BYTES;
        if (stg >= NSTAGE * STAGE_BYTES) stg = 0;
    }

    // Epilogue: lane l = 4g+t -> rows g, g+8; cols 2t, 2t+1
    const int g = lane >> 2;
    const int t2 = (lane & 3) * 2;
#pragma unroll
    for (int im = 0; im < 2; im++) {
        int r0 = warp_m * 32 + im * 16 + g;
#pragma unroll
        for (int j = 0; j < 8; j++) {
            int cc = warp_n * 64 + j * 8 + t2;
            float* p0 = Co + (size_t)r0 * sC + cc;
            if (r0 < nrow) {
                if (cc < ncol)     p0[0] = acc[im][j][0];
                if (cc + 1 < ncol) p0[1] = acc[im][j][1];
            }
            if (r0 + 8 < nrow) {
                float* p1 = p0 + 8 * sC;
                if (cc < ncol)     p1[0] = acc[im][j][2];
                if (cc + 1 < ncol) p1[1] = acc[im][j][3];
            }
        }
    }
}

// ---------------------------------------------------------------------------
// GEMM1: scores[b,y,l] = U_w[y,:] . x[b,l,:]  (M=Y, N=L, K=D)
// ---------------------------------------------------------------------------
__global__ __launch_bounds__(256, 2)
void gemm1_tc(float* __restrict__ scores) {
    const int b  = blockIdx.z;
    const int m0 = blockIdx.y * 128;
    const int n0 = blockIdx.x * 128;
    int nA = min(Y - m0, 128);
    int nB = min(L - n0, 128);
    gemm_core<D / KC, D, D, UOFFE>(
        g_U2 + (size_t)m0 * D, nA,
        g_x2 + ((size_t)b * L + n0) * D, nB,
        scores + ((size_t)b * Y + m0) * L + n0, L, nA, nB);
}

// ---------------------------------------------------------------------------
// GEMM2: m[b,y,d] = alpha[b,y,:] . xT[b,d,:]  (M=Y, N=D, K=LP)
// ---------------------------------------------------------------------------
__global__ __launch_bounds__(256, 2)
void gemm2_tc(float* __restrict__ mout) {
    const int b  = blockIdx.z;
    const int m0 = blockIdx.y * 128;
    const int n0 = blockIdx.x * 128;
    int nA = min(Y - m0, 128);
    gemm_core<LP / KC, LP, LP, AOFFE2>(
        g_a2 + ((size_t)b * Y + m0) * LP, nA,
        g_xT2 + ((size_t)b * D + n0) * LP, 128,
        mout + ((size_t)b * Y + m0) * D + n0, D, nA, 128);
}

// ---------------------------------------------------------------------------
// Splitters / transpose
// ---------------------------------------------------------------------------
__global__ __launch_bounds__(256)
void split_u(const float* __restrict__ src) {
    size_t n = UOFFE;
    for (size_t i = (size_t)blockIdx.x * 256 + threadIdx.x; i < n; i += (size_t)gridDim.x * 256) {
        float v = src[i];
        __half h = __float2half(v);
        float r = v - __half2float(h);
        g_U2[i] = h;
        g_U2[i + UOFFE] = __float2half(r);
    }
}

__global__ __launch_bounds__(256)
void split_x(const float* __restrict__ src) {
    size_t n = XOFFE;
    for (size_t i = (size_t)blockIdx.x * 256 + threadIdx.x; i < n; i += (size_t)gridDim.x * 256) {
        g_x2[i] = __float2half(src[i]);
    }
}

__global__ __launch_bounds__(256)
void transpose_x(const float* __restrict__ x) {
    __shared__ float t[32][33];
    const int b  = blockIdx.z;
    const int l0 = blockIdx.x * 32;
    const int d0 = blockIdx.y * 32;
    const float* xb = x + (size_t)b * L * D;
    const int tx = threadIdx.x & 31;
    const int ty = threadIdx.x >> 5;   // 0..7
#pragma unroll
    for (int i = ty; i < 32; i += 8) {
        int l = l0 + i;
        t[i][tx] = (l < L) ? xb[(size_t)l * D + d0 + tx] : 0.0f;
    }
    __syncthreads();
#pragma unroll
    for (int i = ty; i < 32; i += 8) {
        int d = d0 + i;
        int l = l0 + tx;
        size_t o = ((size_t)b * D + d) * LP + l;
        g_xT2[o] = __float2half(t[tx][i]);
    }
}

// ---------------------------------------------------------------------------
// Softmax over L per row (in place, fp32) + fp16 hi/lo split output (padded)
// ---------------------------------------------------------------------------
__global__ __launch_bounds__(256)
void softmax_rows(float* __restrict__ a) {
    const int row = blockIdx.x;
    float* p = a + (size_t)row * L;
    const int tid = threadIdx.x;

    float vals[10];
    int cnt = 0;
    float mx = -INFINITY;
    for (int i = tid; i < L; i += 256) {
        float v = p[i];
        vals[cnt++] = v;
        mx = fmaxf(mx, v);
    }
    __shared__ float red[256];
    red[tid] = mx; __syncthreads();
    for (int s = 128; s > 0; s >>= 1) {
        if (tid < s) red[tid] = fmaxf(red[tid], red[tid + s]);
        __syncthreads();
    }
    mx = red[0];
    __syncthreads();

    float sum = 0.f;
    for (int c = 0; c < cnt; c++) {
        vals[c] = expf(vals[c] - mx);
        sum += vals[c];
    }
    red[tid] = sum; __syncthreads();
    for (int s = 128; s > 0; s >>= 1) {
        if (tid < s) red[tid] += red[tid + s];
        __syncthreads();
    }
    float inv = 1.0f / red[0];

    size_t ob = (size_t)row * LP;
    cnt = 0;
    for (int i = tid; i < L; i += 256) {
        float v = vals[cnt++] * inv;
        p[i] = v;
        __half h = __float2half(v);
        float r = v - __half2float(h);
        g_a2[ob + i] = h;
        g_a2[ob + i + AOFFE2] = __float2half(r);
    }
    __half z = __float2half(0.0f);
    for (int i = L + tid; i < LP; i += 256) {
        g_a2[ob + i] = z;
        g_a2[ob + i + AOFFE2] = z;
    }
}

// ---------------------------------------------------------------------------
// Final dot + BCE term per row; loss reduce
// ---------------------------------------------------------------------------
__global__ __launch_bounds__(128)
void final_kernel(const float* __restrict__ mrr,
                  const float* __restrict__ fw,
                  const float* __restrict__ fb,
                  const float* __restrict__ target,
                  float* __restrict__ out_y) {
    const int r = blockIdx.x;
    const int i = r % Y;
    const float* mp = mrr + (size_t)r * D;
    const float* wp = fw + (size_t)i * D;
    const int tid = threadIdx.x;

    float s = 0.f;
    for (int d = tid; d < D; d += 128) s = fmaf(wp[d], mp[d], s);
#pragma unroll
    for (int off = 16; off > 0; off >>= 1) s += __shfl_down_sync(0xffffffffu, s, off);

    __shared__ float sh[4];
    if ((tid & 31) == 0) sh[tid >> 5] = s;
    __syncthreads();
    if (tid == 0) {
        float yv = sh[0] + sh[1] + sh[2] + sh[3] + fb[i];
        out_y[r] = yv;
        float t = target[r];
        g_bce[r] = fmaxf(yv, 0.f) - yv * t + log1pf(expf(-fabsf(yv)));
    }
}

__global__ __launch_bounds__(256)
void loss_reduce(float* __restrict__ out_loss) {
    __shared__ double sh[256];
    double s = 0.0;
    for (int i = threadIdx.x; i < B * Y; i += 256) s += (double)g_bce[i];
    sh[threadIdx.x] = s;
    __syncthreads();
    for (int st = 128; st > 0; st >>= 1) {
        if (threadIdx.x < st) sh[threadIdx.x] += sh[threadIdx.x + st];
        __syncthreads();
    }
    if (threadIdx.x == 0) out_loss[0] = (float)(sh[0] / (double)(B * Y));
}

// ---------------------------------------------------------------------------
// Launch. Output layout: [y (B*Y), loss (1), alpha (B*Y*L), m (B*Y*D)]
// ---------------------------------------------------------------------------
extern "C" void kernel_launch(void* const* d_in, const int* in_sizes, int n_in,
                              void* d_out, int out_size) {
    const float* x      = (const float*)d_in[0];
    const float* target = (const float*)d_in[1];
    // d_in[2] = text_inputs (unused)
    const float* Uw     = (const float*)d_in[3];
    const float* fw     = (const float*)d_in[4];
    const float* fb     = (const float*)d_in[5];

    float* out       = (float*)d_out;
    float* out_y     = out;
    float* out_loss  = out + (size_t)B * Y;
    float* out_alpha = out_loss + 1;
    float* out_m     = out_alpha + (size_t)B * Y * L;

    cudaFuncSetAttribute(gemm1_tc, cudaFuncAttributeMaxDynamicSharedMemorySize, SMEM_BYTES);
    cudaFuncSetAttribute(gemm2_tc, cudaFuncAttributeMaxDynamicSharedMemorySize, SMEM_BYTES);

    split_u<<<2048, 256>>>(Uw);
    split_x<<<8192, 256>>>(x);
    transpose_x<<<dim3(LP / 32, D / 32, B), 256>>>(x);

    gemm1_tc<<<dim3((L + 127) / 128, (Y + 127) / 128, B), 256, SMEM_BYTES>>>(out_alpha);

    softmax_rows<<<B * Y, 256>>>(out_alpha);

    gemm2_tc<<<dim3(D / 128, (Y + 127) / 128, B), 256, SMEM_BYTES>>>(out_m);

    final_kernel<<<B * Y, 128>>>(out_m, fw, fb, target, out_y);
    loss_reduce<<<1, 256>>>(out_loss);
}

// round 12
// speedup vs baseline: 2.1249x; 1.4591x over previous
#include <cuda_runtime.h>
#include <cuda_fp16.h>
#include <math.h>
#include <stdint.h>

// Problem constants
#define B 8
#define L 2500
#define D 512
#define Y 8921
#define LP 2560            // L padded (K of GEMM2)

// GEMM geometry: CTA tile 128(M) x 128(N), K-chunk 64, 8 warps (32x64 each),
// 2 CTAs per SM. Single-pass fp16: C = Ah*Bh (error ~2.6e-4 << 1e-3).
#define KC 64
#define A_OFF 0
#define B_OFF 16384
#define STAGE_BYTES 32768            // A(16K)+B(16K), each 128x64 fp16
#define NSTAGE 3
#define SMEM_BYTES (NSTAGE * STAGE_BYTES)   // 98304/CTA; 2 CTAs = 192KB/SM

// ---------------------------------------------------------------------------
// Device scratch (fp16 hi-only operands)
// ---------------------------------------------------------------------------
#define XOFFE  ((size_t)B * L * D)
#define XTOFFE ((size_t)B * D * LP)
#define UOFFE  ((size_t)Y * D)
#define AOFFE2 ((size_t)B * Y * LP)

__device__ __align__(16) __half g_x2[XOFFE];
__device__ __align__(16) __half g_xT2[XTOFFE];
__device__ __align__(16) __half g_U2[UOFFE];
__device__ __align__(16) __half g_a2[AOFFE2];
__device__ float g_bce[B * Y];

// ---------------------------------------------------------------------------
// PTX helpers (base sm_103-legal)
// ---------------------------------------------------------------------------
__device__ __forceinline__ uint32_t smem_u32(const void* p) {
    uint32_t a;
    asm("{ .reg .u64 t; cvta.to.shared.u64 t, %1; cvt.u32.u64 %0, t; }"
        : "=r"(a) : "l"(p));
    return a;
}
__device__ __forceinline__ void cpa16(uint32_t dst, const void* src, int szbytes) {
    asm volatile("cp.async.cg.shared.global [%0], [%1], 16, %2;"
                 :: "r"(dst), "l"(src), "r"(szbytes) : "memory");
}
__device__ __forceinline__ void cpa_commit() {
    asm volatile("cp.async.commit_group;" ::: "memory");
}
template <int N>
__device__ __forceinline__ void cpa_wait() {
    asm volatile("cp.async.wait_group %0;" :: "n"(N) : "memory");
}
__device__ __forceinline__ void ldsm4(uint32_t* r, uint32_t addr) {
    asm volatile("ldmatrix.sync.aligned.m8n8.x4.shared.b16 {%0,%1,%2,%3}, [%4];"
                 : "=r"(r[0]), "=r"(r[1]), "=r"(r[2]), "=r"(r[3]) : "r"(addr));
}
__device__ __forceinline__ void mma16816(float* c, const uint32_t* a,
                                         uint32_t b0, uint32_t b1) {
    asm volatile(
        "mma.sync.aligned.m16n8k16.row.col.f32.f16.f16.f32 "
        "{%0,%1,%2,%3}, {%4,%5,%6,%7}, {%8,%9}, {%0,%1,%2,%3};"
        : "+f"(c[0]), "+f"(c[1]), "+f"(c[2]), "+f"(c[3])
        : "r"(a[0]), "r"(a[1]), "r"(a[2]), "r"(a[3]), "r"(b0), "r"(b1));
}

// 128B-row XOR swizzle: row r, 16B-chunk c (0..7)
__device__ __forceinline__ uint32_t swz128(int r, int c) {
    return (uint32_t)(r * 128 + ((c ^ (r & 7)) << 4));
}

// ---------------------------------------------------------------------------
// Core GEMM: C[m<=128, n<=128] = sum_k A[m,k]*B[n,k], fp16 in, fp32 acc.
// 256 threads, 8 warps 4(M) x 2(N), warp tile 32x64, m16n8k16.
// KC=64, 3-stage cp.async ring, one barrier/chunk, B-frag double buffer,
// gmem prefetch interleaved into the MMA stream.
// ---------------------------------------------------------------------------
template <int CHUNKS, int SA, int SB>
__device__ __forceinline__ void gemm_core(
    const __half* __restrict__ Asrc, int nA,
    const __half* __restrict__ Bsrc, int nB,
    float* __restrict__ Co, int sC, int nrow, int ncol)
{
    extern __shared__ __align__(128) char smem[];
    const uint32_t sb = smem_u32(smem);
    const int tid = threadIdx.x;
    const int lane = tid & 31;
    const int wid = tid >> 5;
    const int warp_m = wid >> 1;     // 0..3 -> 32-row slabs
    const int warp_n = wid & 1;      // 0..1 -> 64-col slabs
    const int rowsel = lane & 15;
    const int colsel = (lane >> 4) & 1;

    // ---- cp.async per-thread state (compile-time strides)
    const int rT = tid >> 3, cT = tid & 7;     // 32 row-groups x 8 chunks
    uint32_t so[4];
    int szA[4], szB[4];
#pragma unroll
    for (int it = 0; it < 4; it++) {
        int r = rT + it * 32;
        so[it] = swz128(r, cT);
        szA[it] = (r < nA) ? 16 : 0;
        szB[it] = (r < nB) ? 16 : 0;
    }
    const __half* pA = Asrc + (size_t)rT * SA + cT * 8;
    const __half* pB = Bsrc + (size_t)rT * SB + cT * 8;

    auto load_a = [&](uint32_t st) {
#pragma unroll
        for (int it = 0; it < 4; it++)
            cpa16(st + A_OFF + so[it], pA + (size_t)(it * 32) * SA, szA[it]);
        pA += KC;
    };
    auto load_b = [&](uint32_t st) {
#pragma unroll
        for (int it = 0; it < 4; it++)
            cpa16(st + B_OFF + so[it], pB + (size_t)(it * 32) * SB, szB[it]);
        pB += KC;
    };

    // ---- precomputed LDSM offsets
    uint32_t offA[4][2];   // [kk][im]
#pragma unroll
    for (int im = 0; im < 2; im++) {
        int r = warp_m * 32 + im * 16 + rowsel;
#pragma unroll
        for (int kk = 0; kk < 4; kk++)
            offA[kk][im] = (uint32_t)(A_OFF + r * 128 +
                           (((kk * 2 + colsel) ^ (r & 7)) << 4));
    }
    uint32_t offB[4][4];   // [kk][jn]
#pragma unroll
    for (int jn = 0; jn < 4; jn++) {
        int r = warp_n * 64 + jn * 16 + rowsel;
#pragma unroll
        for (int kk = 0; kk < 4; kk++)
            offB[kk][jn] = (uint32_t)(B_OFF + r * 128 +
                           (((kk * 2 + colsel) ^ (r & 7)) << 4));
    }

    float acc[2][8][4];
#pragma unroll
    for (int i = 0; i < 2; i++)
#pragma unroll
        for (int j = 0; j < 8; j++)
#pragma unroll
            for (int q = 0; q < 4; q++) acc[i][j][q] = 0.0f;

    // Prologue: fill stages 0 and 1
    load_a(sb); load_b(sb); cpa_commit();
    if (CHUNKS > 1) { load_a(sb + STAGE_BYTES); load_b(sb + STAGE_BYTES); cpa_commit(); }

    uint32_t aH[2][4];
    uint32_t bHb[2][4];
    uint32_t stg = 0;

#pragma unroll 1
    for (int c = 0; c < CHUNKS; c++) {
        if (c + 1 < CHUNKS) cpa_wait<1>(); else cpa_wait<0>();
        __syncthreads();   // stage c ready; all warps done computing c-1

        const uint32_t s = sb + stg;
        uint32_t pstg = stg + 2 * STAGE_BYTES;
        if (pstg >= NSTAGE * STAGE_BYTES) pstg -= NSTAGE * STAGE_BYTES;
        const uint32_t pf = sb + pstg;
        const bool do_pf = (c + 2 < CHUNKS);

        // initial fragments: A(kk=0), B(kk=0,jn=0)
        ldsm4(aH[0], s + offA[0][0]);
        ldsm4(aH[1], s + offA[0][1]);
        ldsm4(bHb[0], s + offB[0][0]);

#pragma unroll
        for (int kk = 0; kk < 4; kk++) {
#pragma unroll
            for (int jn = 0; jn < 4; jn++) {
                const int p = (kk * 4 + jn) & 1;
                // Prefetch next B fragment (register double-buffer)
                if (!(kk == 3 && jn == 3)) {
                    const int nk = (jn == 3) ? kk + 1 : kk;
                    const int njn = (jn == 3) ? 0 : jn + 1;
                    ldsm4(bHb[p ^ 1], s + offB[nk][njn]);
                }
                // 4 MMAs
                mma16816(acc[0][2 * jn],     aH[0], bHb[p][0], bHb[p][2]);
                mma16816(acc[0][2 * jn + 1], aH[0], bHb[p][1], bHb[p][3]);
                mma16816(acc[1][2 * jn],     aH[1], bHb[p][0], bHb[p][2]);
                mma16816(acc[1][2 * jn + 1], aH[1], bHb[p][1], bHb[p][3]);
                // Interleaved gmem prefetch for chunk c+2
                if (kk == 0 && jn == 1 && do_pf) load_a(pf);
                if (kk == 0 && jn == 2 && do_pf) { load_b(pf); cpa_commit(); }
                // Reload A fragments for next kk after last use
                if (jn == 3 && kk < 3) {
                    ldsm4(aH[0], s + offA[kk + 1][0]);
                    ldsm4(aH[1], s + offA[kk + 1][1]);
                }
            }
        }

        stg += STAGE_BYTES;
        if (stg >= NSTAGE * STAGE_BYTES) stg = 0;
    }

    // Epilogue: lane l = 4g+t -> rows g, g+8; cols 2t, 2t+1
    const int g = lane >> 2;
    const int t2 = (lane & 3) * 2;
#pragma unroll
    for (int im = 0; im < 2; im++) {
        int r0 = warp_m * 32 + im * 16 + g;
#pragma unroll
        for (int j = 0; j < 8; j++) {
            int cc = warp_n * 64 + j * 8 + t2;
            float* p0 = Co + (size_t)r0 * sC + cc;
            if (r0 < nrow) {
                if (cc < ncol)     p0[0] = acc[im][j][0];
                if (cc + 1 < ncol) p0[1] = acc[im][j][1];
            }
            if (r0 + 8 < nrow) {
                float* p1 = p0 + 8 * sC;
                if (cc < ncol)     p1[0] = acc[im][j][2];
                if (cc + 1 < ncol) p1[1] = acc[im][j][3];
            }
        }
    }
}

// ---------------------------------------------------------------------------
// GEMM1: scores[b,y,l] = U_w[y,:] . x[b,l,:]  (M=Y, N=L, K=D)
// ---------------------------------------------------------------------------
__global__ __launch_bounds__(256, 2)
void gemm1_tc(float* __restrict__ scores) {
    const int b  = blockIdx.z;
    const int m0 = blockIdx.y * 128;
    const int n0 = blockIdx.x * 128;
    int nA = min(Y - m0, 128);
    int nB = min(L - n0, 128);
    gemm_core<D / KC, D, D>(
        g_U2 + (size_t)m0 * D, nA,
        g_x2 + ((size_t)b * L + n0) * D, nB,
        scores + ((size_t)b * Y + m0) * L + n0, L, nA, nB);
}

// ---------------------------------------------------------------------------
// GEMM2: m[b,y,d] = alpha[b,y,:] . xT[b,d,:]  (M=Y, N=D, K=LP)
// ---------------------------------------------------------------------------
__global__ __launch_bounds__(256, 2)
void gemm2_tc(float* __restrict__ mout) {
    const int b  = blockIdx.z;
    const int m0 = blockIdx.y * 128;
    const int n0 = blockIdx.x * 128;
    int nA = min(Y - m0, 128);
    gemm_core<LP / KC, LP, LP>(
        g_a2 + ((size_t)b * Y + m0) * LP, nA,
        g_xT2 + ((size_t)b * D + n0) * LP, 128,
        mout + ((size_t)b * Y + m0) * D + n0, D, nA, 128);
}

// ---------------------------------------------------------------------------
// Converters / transpose
// ---------------------------------------------------------------------------
__global__ __launch_bounds__(256)
void split_u(const float* __restrict__ src) {
    size_t n = UOFFE;
    for (size_t i = (size_t)blockIdx.x * 256 + threadIdx.x; i < n; i += (size_t)gridDim.x * 256)
        g_U2[i] = __float2half(src[i]);
}

__global__ __launch_bounds__(256)
void split_x(const float* __restrict__ src) {
    size_t n = XOFFE;
    for (size_t i = (size_t)blockIdx.x * 256 + threadIdx.x; i < n; i += (size_t)gridDim.x * 256)
        g_x2[i] = __float2half(src[i]);
}

__global__ __launch_bounds__(256)
void transpose_x(const float* __restrict__ x) {
    __shared__ float t[32][33];
    const int b  = blockIdx.z;
    const int l0 = blockIdx.x * 32;
    const int d0 = blockIdx.y * 32;
    const float* xb = x + (size_t)b * L * D;
    const int tx = threadIdx.x & 31;
    const int ty = threadIdx.x >> 5;   // 0..7
#pragma unroll
    for (int i = ty; i < 32; i += 8) {
        int l = l0 + i;
        t[i][tx] = (l < L) ? xb[(size_t)l * D + d0 + tx] : 0.0f;
    }
    __syncthreads();
#pragma unroll
    for (int i = ty; i < 32; i += 8) {
        int d = d0 + i;
        int l = l0 + tx;
        size_t o = ((size_t)b * D + d) * LP + l;
        g_xT2[o] = __float2half(t[tx][i]);
    }
}

// ---------------------------------------------------------------------------
// Softmax over L per row (in place, fp32) + fp16 output (padded)
// ---------------------------------------------------------------------------
__global__ __launch_bounds__(256)
void softmax_rows(float* __restrict__ a) {
    const int row = blockIdx.x;
    float* p = a + (size_t)row * L;
    const int tid = threadIdx.x;

    float vals[10];
    int cnt = 0;
    float mx = -INFINITY;
    for (int i = tid; i < L; i += 256) {
        float v = p[i];
        vals[cnt++] = v;
        mx = fmaxf(mx, v);
    }
    __shared__ float red[256];
    red[tid] = mx; __syncthreads();
    for (int s = 128; s > 0; s >>= 1) {
        if (tid < s) red[tid] = fmaxf(red[tid], red[tid + s]);
        __syncthreads();
    }
    mx = red[0];
    __syncthreads();

    float sum = 0.f;
    for (int c = 0; c < cnt; c++) {
        vals[c] = expf(vals[c] - mx);
        sum += vals[c];
    }
    red[tid] = sum; __syncthreads();
    for (int s = 128; s > 0; s >>= 1) {
        if (tid < s) red[tid] += red[tid + s];
        __syncthreads();
    }
    float inv = 1.0f / red[0];

    size_t ob = (size_t)row * LP;
    cnt = 0;
    for (int i = tid; i < L; i += 256) {
        float v = vals[cnt++] * inv;
        p[i] = v;
        g_a2[ob + i] = __float2half(v);
    }
    __half z = __float2half(0.0f);
    for (int i = L + tid; i < LP; i += 256)
        g_a2[ob + i] = z;
}

// ---------------------------------------------------------------------------
// Final dot + BCE term per row; loss reduce
// ---------------------------------------------------------------------------
__global__ __launch_bounds__(128)
void final_kernel(const float* __restrict__ mrr,
                  const float* __restrict__ fw,
                  const float* __restrict__ fb,
                  const float* __restrict__ target,
                  float* __restrict__ out_y) {
    const int r = blockIdx.x;
    const int i = r % Y;
    const float* mp = mrr + (size_t)r * D;
    const float* wp = fw + (size_t)i * D;
    const int tid = threadIdx.x;

    float s = 0.f;
    for (int d = tid; d < D; d += 128) s = fmaf(wp[d], mp[d], s);
#pragma unroll
    for (int off = 16; off > 0; off >>= 1) s += __shfl_down_sync(0xffffffffu, s, off);

    __shared__ float sh[4];
    if ((tid & 31) == 0) sh[tid >> 5] = s;
    __syncthreads();
    if (tid == 0) {
        float yv = sh[0] + sh[1] + sh[2] + sh[3] + fb[i];
        out_y[r] = yv;
        float t = target[r];
        g_bce[r] = fmaxf(yv, 0.f) - yv * t + log1pf(expf(-fabsf(yv)));
    }
}

__global__ __launch_bounds__(256)
void loss_reduce(float* __restrict__ out_loss) {
    __shared__ double sh[256];
    double s = 0.0;
    for (int i = threadIdx.x; i < B * Y; i += 256) s += (double)g_bce[i];
    sh[threadIdx.x] = s;
    __syncthreads();
    for (int st = 128; st > 0; st >>= 1) {
        if (threadIdx.x < st) sh[threadIdx.x] += sh[threadIdx.x + st];
        __syncthreads();
    }
    if (threadIdx.x == 0) out_loss[0] = (float)(sh[0] / (double)(B * Y));
}

// ---------------------------------------------------------------------------
// Launch. Output layout: [y (B*Y), loss (1), alpha (B*Y*L), m (B*Y*D)]
// ---------------------------------------------------------------------------
extern "C" void kernel_launch(void* const* d_in, const int* in_sizes, int n_in,
                              void* d_out, int out_size) {
    const float* x      = (const float*)d_in[0];
    const float* target = (const float*)d_in[1];
    // d_in[2] = text_inputs (unused)
    const float* Uw     = (const float*)d_in[3];
    const float* fw     = (const float*)d_in[4];
    const float* fb     = (const float*)d_in[5];

    float* out       = (float*)d_out;
    float* out_y     = out;
    float* out_loss  = out + (size_t)B * Y;
    float* out_alpha = out_loss + 1;
    float* out_m     = out_alpha + (size_t)B * Y * L;

    cudaFuncSetAttribute(gemm1_tc, cudaFuncAttributeMaxDynamicSharedMemorySize, SMEM_BYTES);
    cudaFuncSetAttribute(gemm2_tc, cudaFuncAttributeMaxDynamicSharedMemorySize, SMEM_BYTES);

    split_u<<<2048, 256>>>(Uw);
    split_x<<<8192, 256>>>(x);
    transpose_x<<<dim3(LP / 32, D / 32, B), 256>>>(x);

    gemm1_tc<<<dim3((L + 127) / 128, (Y + 127) / 128, B), 256, SMEM_BYTES>>>(out_alpha);

    softmax_rows<<<B * Y, 256>>>(out_alpha);

    gemm2_tc<<<dim3(D / 128, (Y + 127) / 128, B), 256, SMEM_BYTES>>>(out_m);

    final_kernel<<<B * Y, 128>>>(out_m, fw, fb, target, out_y);
    loss_reduce<<<1, 256>>>(out_loss);
}

// round 13
// speedup vs baseline: 2.2643x; 1.0656x over previous
#include <cuda_runtime.h>
#include <cuda_fp16.h>
#include <math.h>
#include <stdint.h>

// Problem constants
#define B 8
#define L 2500
#define D 512
#define Y 8921
#define LP 2560            // L padded (K of GEMM2)

// GEMM geometry: CTA tile 128(M) x 128(N), K-chunk 64, 8 warps (32x64 each),
// 2 CTAs per SM. Single-pass fp16. B frags triple-buffered, A frags double.
#define KC 64
#define A_OFF 0
#define B_OFF 16384
#define STAGE_BYTES 32768            // A(16K)+B(16K), each 128x64 fp16
#define NSTAGE 3
#define SMEM_BYTES (NSTAGE * STAGE_BYTES)   // 98304/CTA; 2 CTAs = 192KB/SM

// ---------------------------------------------------------------------------
// Device scratch (fp16 operands + fp16 scores)
// ---------------------------------------------------------------------------
#define XOFFE  ((size_t)B * L * D)
#define XTOFFE ((size_t)B * D * LP)
#define UOFFE  ((size_t)Y * D)
#define AOFFE2 ((size_t)B * Y * LP)
#define SOFFE  ((size_t)B * Y * L)

__device__ __align__(16) __half g_x2[XOFFE];
__device__ __align__(16) __half g_xT2[XTOFFE];
__device__ __align__(16) __half g_U2[UOFFE];
__device__ __align__(16) __half g_a2[AOFFE2];
__device__ __align__(16) __half g_s16[SOFFE];   // fp16 scores (gemm1 out)
__device__ float g_bce[B * Y];

// ---------------------------------------------------------------------------
// PTX helpers (base sm_103-legal)
// ---------------------------------------------------------------------------
__device__ __forceinline__ uint32_t smem_u32(const void* p) {
    uint32_t a;
    asm("{ .reg .u64 t; cvta.to.shared.u64 t, %1; cvt.u32.u64 %0, t; }"
        : "=r"(a) : "l"(p));
    return a;
}
__device__ __forceinline__ void cpa16(uint32_t dst, const void* src, int szbytes) {
    asm volatile("cp.async.cg.shared.global [%0], [%1], 16, %2;"
                 :: "r"(dst), "l"(src), "r"(szbytes) : "memory");
}
__device__ __forceinline__ void cpa_commit() {
    asm volatile("cp.async.commit_group;" ::: "memory");
}
template <int N>
__device__ __forceinline__ void cpa_wait() {
    asm volatile("cp.async.wait_group %0;" :: "n"(N) : "memory");
}
__device__ __forceinline__ void ldsm4(uint32_t* r, uint32_t addr) {
    asm volatile("ldmatrix.sync.aligned.m8n8.x4.shared.b16 {%0,%1,%2,%3}, [%4];"
                 : "=r"(r[0]), "=r"(r[1]), "=r"(r[2]), "=r"(r[3]) : "r"(addr));
}
__device__ __forceinline__ void mma16816(float* c, const uint32_t* a,
                                         uint32_t b0, uint32_t b1) {
    asm volatile(
        "mma.sync.aligned.m16n8k16.row.col.f32.f16.f16.f32 "
        "{%0,%1,%2,%3}, {%4,%5,%6,%7}, {%8,%9}, {%0,%1,%2,%3};"
        : "+f"(c[0]), "+f"(c[1]), "+f"(c[2]), "+f"(c[3])
        : "r"(a[0]), "r"(a[1]), "r"(a[2]), "r"(a[3]), "r"(b0), "r"(b1));
}

// 128B-row XOR swizzle: row r, 16B-chunk c (0..7)
__device__ __forceinline__ uint32_t swz128(int r, int c) {
    return (uint32_t)(r * 128 + ((c ^ (r & 7)) << 4));
}

// ---------------------------------------------------------------------------
// Core GEMM: C[m<=128, n<=128] = sum_k A[m,k]*B[n,k], fp16 in, fp32 acc.
// 256 threads, 8 warps 4(M) x 2(N), warp tile 32x64, m16n8k16.
// KC=64, 3-stage cp.async ring; B frags triple-buffered (lookahead 2 phases),
// A frags double-buffered (reload 2 phases before use).
// OutT = float (fp32 out) or __half (fp16 out).
// ---------------------------------------------------------------------------
template <int CHUNKS, int SA, int SB, typename OutT>
__device__ __forceinline__ void gemm_core(
    const __half* __restrict__ Asrc, int nA,
    const __half* __restrict__ Bsrc, int nB,
    OutT* __restrict__ Co, int sC, int nrow, int ncol)
{
    extern __shared__ __align__(128) char smem[];
    const uint32_t sb = smem_u32(smem);
    const int tid = threadIdx.x;
    const int lane = tid & 31;
    const int wid = tid >> 5;
    const int warp_m = wid >> 1;     // 0..3 -> 32-row slabs
    const int warp_n = wid & 1;      // 0..1 -> 64-col slabs
    const int rowsel = lane & 15;
    const int colsel = (lane >> 4) & 1;

    // ---- cp.async per-thread state (compile-time strides)
    const int rT = tid >> 3, cT = tid & 7;     // 32 row-groups x 8 chunks
    uint32_t so[4];
    int szA[4], szB[4];
#pragma unroll
    for (int it = 0; it < 4; it++) {
        int r = rT + it * 32;
        so[it] = swz128(r, cT);
        szA[it] = (r < nA) ? 16 : 0;
        szB[it] = (r < nB) ? 16 : 0;
    }
    const __half* pA = Asrc + (size_t)rT * SA + cT * 8;
    const __half* pB = Bsrc + (size_t)rT * SB + cT * 8;

    auto load_a = [&](uint32_t st) {
#pragma unroll
        for (int it = 0; it < 4; it++)
            cpa16(st + A_OFF + so[it], pA + (size_t)(it * 32) * SA, szA[it]);
        pA += KC;
    };
    auto load_b = [&](uint32_t st) {
#pragma unroll
        for (int it = 0; it < 4; it++)
            cpa16(st + B_OFF + so[it], pB + (size_t)(it * 32) * SB, szB[it]);
        pB += KC;
    };

    // ---- per-lane LDSM bases + XOR keys (computed inline per use)
    uint32_t aBase[2]; int aX[2];
#pragma unroll
    for (int im = 0; im < 2; im++) {
        int r = warp_m * 32 + im * 16 + rowsel;
        aBase[im] = (uint32_t)(A_OFF + r * 128); aX[im] = r & 7;
    }
    uint32_t bBase[4]; int bX[4];
#pragma unroll
    for (int jn = 0; jn < 4; jn++) {
        int r = warp_n * 64 + jn * 16 + rowsel;
        bBase[jn] = (uint32_t)(B_OFF + r * 128); bX[jn] = r & 7;
    }
#define OFF_A(kk, im) (aBase[im] + (uint32_t)((((kk) * 2 + colsel) ^ aX[im]) << 4))
#define OFF_B(kk, jn) (bBase[jn] + (uint32_t)((((kk) * 2 + colsel) ^ bX[jn]) << 4))

    float acc[2][8][4];
#pragma unroll
    for (int i = 0; i < 2; i++)
#pragma unroll
        for (int j = 0; j < 8; j++)
#pragma unroll
            for (int q = 0; q < 4; q++) acc[i][j][q] = 0.0f;

    // Prologue: fill stages 0 and 1
    load_a(sb); load_b(sb); cpa_commit();
    if (CHUNKS > 1) { load_a(sb + STAGE_BYTES); load_b(sb + STAGE_BYTES); cpa_commit(); }

    uint32_t aHd[2][2][4];   // [buf][im][4]
    uint32_t bHb[3][4];      // triple buffer
    uint32_t stg = 0;

#pragma unroll 1
    for (int c = 0; c < CHUNKS; c++) {
        if (c + 1 < CHUNKS) cpa_wait<1>(); else cpa_wait<0>();
        __syncthreads();   // stage c ready; all warps done computing c-1

        const uint32_t s = sb + stg;
        uint32_t pstg = stg + 2 * STAGE_BYTES;
        if (pstg >= NSTAGE * STAGE_BYTES) pstg -= NSTAGE * STAGE_BYTES;
        const uint32_t pf = sb + pstg;
        const bool do_pf = (c + 2 < CHUNKS);

        // initial fragments: A(kk=0) into buf0; B phases 0 and 1
        ldsm4(aHd[0][0], s + OFF_A(0, 0));
        ldsm4(aHd[0][1], s + OFF_A(0, 1));
        ldsm4(bHb[0], s + OFF_B(0, 0));
        ldsm4(bHb[1], s + OFF_B(0, 1));

        // 16 phases: ph = kk*4 + jn
#pragma unroll
        for (int ph = 0; ph < 16; ph++) {
            const int kk = ph >> 2, jn = ph & 3;
            const int p = ph % 3;
            // Prefetch B fragment 2 phases ahead
            if (ph + 2 < 16) {
                const int nph = ph + 2;
                ldsm4(bHb[nph % 3], s + OFF_B(nph >> 2, nph & 3));
            }
            // 4 MMAs on current fragments
            const uint32_t (*aC)[4] = aHd[kk & 1];
            mma16816(acc[0][2 * jn],     aC[0], bHb[p][0], bHb[p][2]);
            mma16816(acc[0][2 * jn + 1], aC[0], bHb[p][1], bHb[p][3]);
            mma16816(acc[1][2 * jn],     aC[1], bHb[p][0], bHb[p][2]);
            mma16816(acc[1][2 * jn + 1], aC[1], bHb[p][1], bHb[p][3]);
            // Reload A for kk+1 into alternate buffer, 2 phases before use
            if (jn == 1 && kk < 3) {
                ldsm4(aHd[(kk + 1) & 1][0], s + OFF_A(kk + 1, 0));
                ldsm4(aHd[(kk + 1) & 1][1], s + OFF_A(kk + 1, 1));
            }
            // Interleaved gmem prefetch for chunk c+2
            if (ph == 1 && do_pf) load_a(pf);
            if (ph == 2 && do_pf) { load_b(pf); cpa_commit(); }
        }

        stg += STAGE_BYTES;
        if (stg >= NSTAGE * STAGE_BYTES) stg = 0;
    }

    // Epilogue: lane l = 4g+t -> rows g, g+8; cols 2t, 2t+1
    const int g = lane >> 2;
    const int t2 = (lane & 3) * 2;
#pragma unroll
    for (int im = 0; im < 2; im++) {
        int r0 = warp_m * 32 + im * 16 + g;
#pragma unroll
        for (int j = 0; j < 8; j++) {
            int cc = warp_n * 64 + j * 8 + t2;
#pragma unroll
            for (int hv = 0; hv < 2; hv++) {
                int rr = r0 + hv * 8;
                if (rr >= nrow) continue;
                OutT* pr = Co + (size_t)rr * sC;
                float v0 = acc[im][j][hv * 2 + 0];
                float v1 = acc[im][j][hv * 2 + 1];
                if (cc + 1 < ncol) {
                    if constexpr (sizeof(OutT) == 2) {
                        *reinterpret_cast<__half2*>(pr + cc) =
                            __floats2half2_rn(v0, v1);
                    } else {
                        pr[cc] = v0; pr[cc + 1] = v1;
                    }
                } else if (cc < ncol) {
                    if constexpr (sizeof(OutT) == 2) pr[cc] = __float2half(v0);
                    else                             pr[cc] = v0;
                }
            }
        }
    }
#undef OFF_A
#undef OFF_B
}

// ---------------------------------------------------------------------------
// GEMM1: scores16[b,y,l] = fp16( U_w[y,:] . x[b,l,:] )  (M=Y, N=L, K=D)
// ---------------------------------------------------------------------------
__global__ __launch_bounds__(256, 2)
void gemm1_tc() {
    const int b  = blockIdx.z;
    const int m0 = blockIdx.y * 128;
    const int n0 = blockIdx.x * 128;
    int nA = min(Y - m0, 128);
    int nB = min(L - n0, 128);
    gemm_core<D / KC, D, D, __half>(
        g_U2 + (size_t)m0 * D, nA,
        g_x2 + ((size_t)b * L + n0) * D, nB,
        g_s16 + ((size_t)b * Y + m0) * L + n0, L, nA, nB);
}

// ---------------------------------------------------------------------------
// GEMM2: m[b,y,d] = alpha[b,y,:] . xT[b,d,:]  (M=Y, N=D, K=LP)
// ---------------------------------------------------------------------------
__global__ __launch_bounds__(256, 2)
void gemm2_tc(float* __restrict__ mout) {
    const int b  = blockIdx.z;
    const int m0 = blockIdx.y * 128;
    const int n0 = blockIdx.x * 128;
    int nA = min(Y - m0, 128);
    gemm_core<LP / KC, LP, LP, float>(
        g_a2 + ((size_t)b * Y + m0) * LP, nA,
        g_xT2 + ((size_t)b * D + n0) * LP, 128,
        mout + ((size_t)b * Y + m0) * D + n0, D, nA, 128);
}

// ---------------------------------------------------------------------------
// Converters / transpose
// ---------------------------------------------------------------------------
__global__ __launch_bounds__(256)
void split_u(const float* __restrict__ src) {
    size_t n = UOFFE;
    for (size_t i = (size_t)blockIdx.x * 256 + threadIdx.x; i < n; i += (size_t)gridDim.x * 256)
        g_U2[i] = __float2half(src[i]);
}

__global__ __launch_bounds__(256)
void split_x(const float* __restrict__ src) {
    size_t n = XOFFE;
    for (size_t i = (size_t)blockIdx.x * 256 + threadIdx.x; i < n; i += (size_t)gridDim.x * 256)
        g_x2[i] = __float2half(src[i]);
}

__global__ __launch_bounds__(256)
void transpose_x(const float* __restrict__ x) {
    __shared__ float t[32][33];
    const int b  = blockIdx.z;
    const int l0 = blockIdx.x * 32;
    const int d0 = blockIdx.y * 32;
    const float* xb = x + (size_t)b * L * D;
    const int tx = threadIdx.x & 31;
    const int ty = threadIdx.x >> 5;   // 0..7
#pragma unroll
    for (int i = ty; i < 32; i += 8) {
        int l = l0 + i;
        t[i][tx] = (l < L) ? xb[(size_t)l * D + d0 + tx] : 0.0f;
    }
    __syncthreads();
#pragma unroll
    for (int i = ty; i < 32; i += 8) {
        int d = d0 + i;
        int l = l0 + tx;
        size_t o = ((size_t)b * D + d) * LP + l;
        g_xT2[o] = __float2half(t[tx][i]);
    }
}

// ---------------------------------------------------------------------------
// Softmax over L per row: read fp16 scores, write fp32 alpha + fp16 a2 (padded)
// ---------------------------------------------------------------------------
__global__ __launch_bounds__(256)
void softmax_rows(float* __restrict__ alpha) {
    const int row = blockIdx.x;
    const __half* p16 = g_s16 + (size_t)row * L;
    float* pout = alpha + (size_t)row * L;
    const int tid = threadIdx.x;

    float vals[10];
    int cnt = 0;
    float mx = -INFINITY;
    for (int i = tid; i < L; i += 256) {
        float v = __half2float(p16[i]);
        vals[cnt++] = v;
        mx = fmaxf(mx, v);
    }
    __shared__ float red[256];
    red[tid] = mx; __syncthreads();
    for (int s = 128; s > 0; s >>= 1) {
        if (tid < s) red[tid] = fmaxf(red[tid], red[tid + s]);
        __syncthreads();
    }
    mx = red[0];
    __syncthreads();

    float sum = 0.f;
    for (int c = 0; c < cnt; c++) {
        vals[c] = expf(vals[c] - mx);
        sum += vals[c];
    }
    red[tid] = sum; __syncthreads();
    for (int s = 128; s > 0; s >>= 1) {
        if (tid < s) red[tid] += red[tid + s];
        __syncthreads();
    }
    float inv = 1.0f / red[0];

    size_t ob = (size_t)row * LP;
    cnt = 0;
    for (int i = tid; i < L; i += 256) {
        float v = vals[cnt++] * inv;
        pout[i] = v;
        g_a2[ob + i] = __float2half(v);
    }
    __half z = __float2half(0.0f);
    for (int i = L + tid; i < LP; i += 256)
        g_a2[ob + i] = z;
}

// ---------------------------------------------------------------------------
// Final dot + BCE term per row; loss reduce
// ---------------------------------------------------------------------------
__global__ __launch_bounds__(128)
void final_kernel(const float* __restrict__ mrr,
                  const float* __restrict__ fw,
                  const float* __restrict__ fb,
                  const float* __restrict__ target,
                  float* __restrict__ out_y) {
    const int r = blockIdx.x;
    const int i = r % Y;
    const float* mp = mrr + (size_t)r * D;
    const float* wp = fw + (size_t)i * D;
    const int tid = threadIdx.x;

    float s = 0.f;
    for (int d = tid; d < D; d += 128) s = fmaf(wp[d], mp[d], s);
#pragma unroll
    for (int off = 16; off > 0; off >>= 1) s += __shfl_down_sync(0xffffffffu, s, off);

    __shared__ float sh[4];
    if ((tid & 31) == 0) sh[tid >> 5] = s;
    __syncthreads();
    if (tid == 0) {
        float yv = sh[0] + sh[1] + sh[2] + sh[3] + fb[i];
        out_y[r] = yv;
        float t = target[r];
        g_bce[r] = fmaxf(yv, 0.f) - yv * t + log1pf(expf(-fabsf(yv)));
    }
}

__global__ __launch_bounds__(256)
void loss_reduce(float* __restrict__ out_loss) {
    __shared__ double sh[256];
    double s = 0.0;
    for (int i = threadIdx.x; i < B * Y; i += 256) s += (double)g_bce[i];
    sh[threadIdx.x] = s;
    __syncthreads();
    for (int st = 128; st > 0; st >>= 1) {
        if (threadIdx.x < st) sh[threadIdx.x] += sh[threadIdx.x + st];
        __syncthreads();
    }
    if (threadIdx.x == 0) out_loss[0] = (float)(sh[0] / (double)(B * Y));
}

// ---------------------------------------------------------------------------
// Launch. Output layout: [y (B*Y), loss (1), alpha (B*Y*L), m (B*Y*D)]
// ---------------------------------------------------------------------------
extern "C" void kernel_launch(void* const* d_in, const int* in_sizes, int n_in,
                              void* d_out, int out_size) {
    const float* x      = (const float*)d_in[0];
    const float* target = (const float*)d_in[1];
    // d_in[2] = text_inputs (unused)
    const float* Uw     = (const float*)d_in[3];
    const float* fw     = (const float*)d_in[4];
    const float* fb     = (const float*)d_in[5];

    float* out       = (float*)d_out;
    float* out_y     = out;
    float* out_loss  = out + (size_t)B * Y;
    float* out_alpha = out_loss + 1;
    float* out_m     = out_alpha + (size_t)B * Y * L;

    cudaFuncSetAttribute(gemm1_tc, cudaFuncAttributeMaxDynamicSharedMemorySize, SMEM_BYTES);
    cudaFuncSetAttribute(gemm2_tc, cudaFuncAttributeMaxDynamicSharedMemorySize, SMEM_BYTES);

    split_u<<<2048, 256>>>(Uw);
    split_x<<<8192, 256>>>(x);
    transpose_x<<<dim3(LP / 32, D / 32, B), 256>>>(x);

    gemm1_tc<<<dim3((L + 127) / 128, (Y + 127) / 128, B), 256, SMEM_BYTES>>>();

    softmax_rows<<<B * Y, 256>>>(out_alpha);

    gemm2_tc<<<dim3(D / 128, (Y + 127) / 128, B), 256, SMEM_BYTES>>>(out_m);

    final_kernel<<<B * Y, 128>>>(out_m, fw, fb, target, out_y);
    loss_reduce<<<1, 256>>>(out_loss);
}

// round 14
// speedup vs baseline: 2.6207x; 1.1574x over previous
#include <cuda_runtime.h>
#include <cuda_fp16.h>
#include <math.h>
#include <stdint.h>

// Problem constants
#define B 8
#define L 2500
#define D 512
#define Y 8921
#define LP 2560            // L padded (K of GEMM2)

// GEMM geometry: CTA tile 128(M) x 128(N), K-chunk 64, 8 warps (32x64 each),
// 2 CTAs per SM. Single-pass fp16. B frags triple-buffered, A frags double.
#define KC 64
#define A_OFF 0
#define B_OFF 16384
#define STAGE_BYTES 32768            // A(16K)+B(16K), each 128x64 fp16
#define NSTAGE 3
#define SMEM_BYTES (NSTAGE * STAGE_BYTES)   // 98304/CTA; 2 CTAs = 192KB/SM

// ---------------------------------------------------------------------------
// Device scratch
// ---------------------------------------------------------------------------
#define XOFFE  ((size_t)B * L * D)
#define XTOFFE ((size_t)B * D * LP)
#define UOFFE  ((size_t)Y * D)
#define AOFFE2 ((size_t)B * Y * LP)
#define SOFFE  ((size_t)B * Y * L)

__device__ __align__(16) __half g_x2[XOFFE];
__device__ __align__(16) __half g_xT2[XTOFFE];
__device__ __align__(16) __half g_U2[UOFFE];
__device__ __align__(16) __half g_a2[AOFFE2];
__device__ __align__(16) __half g_s16[SOFFE];    // fp16 scores (gemm1 out)
__device__ __align__(16) float g_ypart[(size_t)B * Y * 4];  // per-dblock dots
__device__ float g_bce[B * Y];

// ---------------------------------------------------------------------------
// PTX helpers (base sm_103-legal)
// ---------------------------------------------------------------------------
__device__ __forceinline__ uint32_t smem_u32(const void* p) {
    uint32_t a;
    asm("{ .reg .u64 t; cvta.to.shared.u64 t, %1; cvt.u32.u64 %0, t; }"
        : "=r"(a) : "l"(p));
    return a;
}
__device__ __forceinline__ void cpa16(uint32_t dst, const void* src, int szbytes) {
    asm volatile("cp.async.cg.shared.global [%0], [%1], 16, %2;"
                 :: "r"(dst), "l"(src), "r"(szbytes) : "memory");
}
__device__ __forceinline__ void cpa_commit() {
    asm volatile("cp.async.commit_group;" ::: "memory");
}
template <int N>
__device__ __forceinline__ void cpa_wait() {
    asm volatile("cp.async.wait_group %0;" :: "n"(N) : "memory");
}
__device__ __forceinline__ void ldsm4(uint32_t* r, uint32_t addr) {
    asm volatile("ldmatrix.sync.aligned.m8n8.x4.shared.b16 {%0,%1,%2,%3}, [%4];"
                 : "=r"(r[0]), "=r"(r[1]), "=r"(r[2]), "=r"(r[3]) : "r"(addr));
}
__device__ __forceinline__ void mma16816(float* c, const uint32_t* a,
                                         uint32_t b0, uint32_t b1) {
    asm volatile(
        "mma.sync.aligned.m16n8k16.row.col.f32.f16.f16.f32 "
        "{%0,%1,%2,%3}, {%4,%5,%6,%7}, {%8,%9}, {%0,%1,%2,%3};"
        : "+f"(c[0]), "+f"(c[1]), "+f"(c[2]), "+f"(c[3])
        : "r"(a[0]), "r"(a[1]), "r"(a[2]), "r"(a[3]), "r"(b0), "r"(b1));
}

// 128B-row XOR swizzle: row r, 16B-chunk c (0..7)
__device__ __forceinline__ uint32_t swz128(int r, int c) {
    return (uint32_t)(r * 128 + ((c ^ (r & 7)) << 4));
}

// ---------------------------------------------------------------------------
// Core GEMM: C[m<=128, n<=128] = sum_k A[m,k]*B[n,k], fp16 in, fp32 acc.
// 256 threads, 8 warps 4(M) x 2(N), warp tile 32x64, m16n8k16.
// FUSE_DOT: additionally emit per-row partial dot with fw into ypart.
// ---------------------------------------------------------------------------
template <int CHUNKS, int SA, int SB, typename OutT, bool FUSE_DOT>
__device__ __forceinline__ void gemm_core(
    const __half* __restrict__ Asrc, int nA,
    const __half* __restrict__ Bsrc, int nB,
    OutT* __restrict__ Co, int sC, int nrow, int ncol,
    const float* __restrict__ fwp,   // fw + m0*D + n0 (FUSE_DOT only)
    float* __restrict__ ypart,       // g_ypart + (b*Y+m0)*4 + nblk
    int dummy)
{
    extern __shared__ __align__(128) char smem[];
    const uint32_t sb = smem_u32(smem);
    const int tid = threadIdx.x;
    const int lane = tid & 31;
    const int wid = tid >> 5;
    const int warp_m = wid >> 1;     // 0..3 -> 32-row slabs
    const int warp_n = wid & 1;      // 0..1 -> 64-col slabs
    const int rowsel = lane & 15;
    const int colsel = (lane >> 4) & 1;

    // ---- cp.async per-thread state (compile-time strides)
    const int rT = tid >> 3, cT = tid & 7;
    uint32_t so[4];
    int szA[4], szB[4];
#pragma unroll
    for (int it = 0; it < 4; it++) {
        int r = rT + it * 32;
        so[it] = swz128(r, cT);
        szA[it] = (r < nA) ? 16 : 0;
        szB[it] = (r < nB) ? 16 : 0;
    }
    const __half* pA = Asrc + (size_t)rT * SA + cT * 8;
    const __half* pB = Bsrc + (size_t)rT * SB + cT * 8;

    auto load_a = [&](uint32_t st) {
#pragma unroll
        for (int it = 0; it < 4; it++)
            cpa16(st + A_OFF + so[it], pA + (size_t)(it * 32) * SA, szA[it]);
        pA += KC;
    };
    auto load_b = [&](uint32_t st) {
#pragma unroll
        for (int it = 0; it < 4; it++)
            cpa16(st + B_OFF + so[it], pB + (size_t)(it * 32) * SB, szB[it]);
        pB += KC;
    };

    // ---- per-lane LDSM bases + XOR keys
    uint32_t aBase[2]; int aX[2];
#pragma unroll
    for (int im = 0; im < 2; im++) {
        int r = warp_m * 32 + im * 16 + rowsel;
        aBase[im] = (uint32_t)(A_OFF + r * 128); aX[im] = r & 7;
    }
    uint32_t bBase[4]; int bX[4];
#pragma unroll
    for (int jn = 0; jn < 4; jn++) {
        int r = warp_n * 64 + jn * 16 + rowsel;
        bBase[jn] = (uint32_t)(B_OFF + r * 128); bX[jn] = r & 7;
    }
#define OFF_A(kk, im) (aBase[im] + (uint32_t)((((kk) * 2 + colsel) ^ aX[im]) << 4))
#define OFF_B(kk, jn) (bBase[jn] + (uint32_t)((((kk) * 2 + colsel) ^ bX[jn]) << 4))

    float acc[2][8][4];
#pragma unroll
    for (int i = 0; i < 2; i++)
#pragma unroll
        for (int j = 0; j < 8; j++)
#pragma unroll
            for (int q = 0; q < 4; q++) acc[i][j][q] = 0.0f;

    // Prologue: fill stages 0 and 1
    load_a(sb); load_b(sb); cpa_commit();
    if (CHUNKS > 1) { load_a(sb + STAGE_BYTES); load_b(sb + STAGE_BYTES); cpa_commit(); }

    uint32_t aHd[2][2][4];
    uint32_t bHb[3][4];
    uint32_t stg = 0;

#pragma unroll 1
    for (int c = 0; c < CHUNKS; c++) {
        if (c + 1 < CHUNKS) cpa_wait<1>(); else cpa_wait<0>();
        __syncthreads();

        const uint32_t s = sb + stg;
        uint32_t pstg = stg + 2 * STAGE_BYTES;
        if (pstg >= NSTAGE * STAGE_BYTES) pstg -= NSTAGE * STAGE_BYTES;
        const uint32_t pf = sb + pstg;
        const bool do_pf = (c + 2 < CHUNKS);

        ldsm4(aHd[0][0], s + OFF_A(0, 0));
        ldsm4(aHd[0][1], s + OFF_A(0, 1));
        ldsm4(bHb[0], s + OFF_B(0, 0));
        ldsm4(bHb[1], s + OFF_B(0, 1));

#pragma unroll
        for (int ph = 0; ph < 16; ph++) {
            const int kk = ph >> 2, jn = ph & 3;
            const int p = ph % 3;
            if (ph + 2 < 16) {
                const int nph = ph + 2;
                ldsm4(bHb[nph % 3], s + OFF_B(nph >> 2, nph & 3));
            }
            const uint32_t (*aC)[4] = aHd[kk & 1];
            mma16816(acc[0][2 * jn],     aC[0], bHb[p][0], bHb[p][2]);
            mma16816(acc[0][2 * jn + 1], aC[0], bHb[p][1], bHb[p][3]);
            mma16816(acc[1][2 * jn],     aC[1], bHb[p][0], bHb[p][2]);
            mma16816(acc[1][2 * jn + 1], aC[1], bHb[p][1], bHb[p][3]);
            if (jn == 1 && kk < 3) {
                ldsm4(aHd[(kk + 1) & 1][0], s + OFF_A(kk + 1, 0));
                ldsm4(aHd[(kk + 1) & 1][1], s + OFF_A(kk + 1, 1));
            }
            if (ph == 1 && do_pf) load_a(pf);
            if (ph == 2 && do_pf) { load_b(pf); cpa_commit(); }
        }

        stg += STAGE_BYTES;
        if (stg >= NSTAGE * STAGE_BYTES) stg = 0;
    }

    // Epilogue: lane l = 4g+t -> rows g, g+8; cols 2t, 2t+1
    const int g = lane >> 2;
    const int t2 = (lane & 3) * 2;
#pragma unroll
    for (int im = 0; im < 2; im++) {
        int r0 = warp_m * 32 + im * 16 + g;
#pragma unroll
        for (int j = 0; j < 8; j++) {
            int cc = warp_n * 64 + j * 8 + t2;
#pragma unroll
            for (int hv = 0; hv < 2; hv++) {
                int rr = r0 + hv * 8;
                if (rr >= nrow) continue;
                OutT* pr = Co + (size_t)rr * sC;
                float v0 = acc[im][j][hv * 2 + 0];
                float v1 = acc[im][j][hv * 2 + 1];
                if (cc + 1 < ncol) {
                    if constexpr (sizeof(OutT) == 2) {
                        *reinterpret_cast<__half2*>(pr + cc) =
                            __floats2half2_rn(v0, v1);
                    } else {
                        pr[cc] = v0; pr[cc + 1] = v1;
                    }
                } else if (cc < ncol) {
                    if constexpr (sizeof(OutT) == 2) pr[cc] = __float2half(v0);
                    else                             pr[cc] = v0;
                }
            }
        }
    }

    if constexpr (FUSE_DOT) {
        // Per-thread partial dot with fw over this thread's 16 cols, 4 rows.
        float part[4];   // [im*2 + hv]
#pragma unroll
        for (int e = 0; e < 4; e++) part[e] = 0.0f;
#pragma unroll
        for (int im = 0; im < 2; im++) {
#pragma unroll
            for (int hv = 0; hv < 2; hv++) {
                int rr = warp_m * 32 + im * 16 + hv * 8 + g;
                if (rr >= nrow) continue;
                const float* fr = fwp + (size_t)rr * D;
                float sacc = 0.f;
#pragma unroll
                for (int j = 0; j < 8; j++) {
                    int cc = warp_n * 64 + j * 8 + t2;
                    float2 w = *reinterpret_cast<const float2*>(fr + cc);
                    sacc = fmaf(w.x, acc[im][j][hv * 2 + 0], sacc);
                    sacc = fmaf(w.y, acc[im][j][hv * 2 + 1], sacc);
                }
                part[im * 2 + hv] = sacc;
            }
        }
        // Reduce across the 4 lanes of each quad (same rows, different cols)
#pragma unroll
        for (int e = 0; e < 4; e++) {
            part[e] += __shfl_xor_sync(0xffffffffu, part[e], 1);
            part[e] += __shfl_xor_sync(0xffffffffu, part[e], 2);
        }
        // Combine warp_n halves via smem, then one write per row
        float* sp = reinterpret_cast<float*>(smem);   // [128][2]
        __syncthreads();   // all warps done with smem stages
        if ((lane & 3) == 0) {
#pragma unroll
            for (int im = 0; im < 2; im++)
#pragma unroll
                for (int hv = 0; hv < 2; hv++) {
                    int rl = warp_m * 32 + im * 16 + hv * 8 + g;
                    sp[rl * 2 + warp_n] = part[im * 2 + hv];
                }
        }
        __syncthreads();
        if (tid < 128 && tid < nrow)
            ypart[(size_t)tid * 4] = sp[tid * 2] + sp[tid * 2 + 1];
    }
#undef OFF_A
#undef OFF_B
}

// ---------------------------------------------------------------------------
// GEMM1: scores16[b,y,l] = fp16( U_w[y,:] . x[b,l,:] )
// ---------------------------------------------------------------------------
__global__ __launch_bounds__(256, 2)
void gemm1_tc() {
    const int b  = blockIdx.z;
    const int m0 = blockIdx.y * 128;
    const int n0 = blockIdx.x * 128;
    int nA = min(Y - m0, 128);
    int nB = min(L - n0, 128);
    gemm_core<D / KC, D, D, __half, false>(
        g_U2 + (size_t)m0 * D, nA,
        g_x2 + ((size_t)b * L + n0) * D, nB,
        g_s16 + ((size_t)b * Y + m0) * L + n0, L, nA, nB,
        nullptr, nullptr, 0);
}

// ---------------------------------------------------------------------------
// GEMM2: m[b,y,d] = alpha . xT ; fused partial dot with final_w
// ---------------------------------------------------------------------------
__global__ __launch_bounds__(256, 2)
void gemm2_tc(float* __restrict__ mout, const float* __restrict__ fw) {
    const int b  = blockIdx.z;
    const int m0 = blockIdx.y * 128;
    const int n0 = blockIdx.x * 128;
    int nA = min(Y - m0, 128);
    gemm_core<LP / KC, LP, LP, float, true>(
        g_a2 + ((size_t)b * Y + m0) * LP, nA,
        g_xT2 + ((size_t)b * D + n0) * LP, 128,
        mout + ((size_t)b * Y + m0) * D + n0, D, nA, 128,
        fw + (size_t)m0 * D + n0,
        g_ypart + ((size_t)b * Y + m0) * 4 + (n0 >> 7), 0);
}

// ---------------------------------------------------------------------------
// Converters: U; fused x -> (g_x2, g_xT2)
// ---------------------------------------------------------------------------
__global__ __launch_bounds__(256)
void split_u(const float* __restrict__ src) {
    size_t n = UOFFE;
    for (size_t i = (size_t)blockIdx.x * 256 + threadIdx.x; i < n; i += (size_t)gridDim.x * 256)
        g_U2[i] = __float2half(src[i]);
}

__global__ __launch_bounds__(256)
void fuse_x(const float* __restrict__ x) {
    __shared__ float t[32][33];
    const int b  = blockIdx.z;
    const int l0 = blockIdx.x * 32;
    const int d0 = blockIdx.y * 32;
    const float* xb = x + (size_t)b * L * D;
    const int tx = threadIdx.x & 31;
    const int ty = threadIdx.x >> 5;   // 0..7
#pragma unroll
    for (int i = ty; i < 32; i += 8) {
        int l = l0 + i;
        float v = (l < L) ? xb[(size_t)l * D + d0 + tx] : 0.0f;
        t[i][tx] = v;
        if (l < L)
            g_x2[((size_t)b * L + l) * D + d0 + tx] = __float2half(v);
    }
    __syncthreads();
#pragma unroll
    for (int i = ty; i < 32; i += 8) {
        int d = d0 + i;
        int l = l0 + tx;
        size_t o = ((size_t)b * D + d) * LP + l;
        g_xT2[o] = __float2half(t[tx][i]);
    }
}

// ---------------------------------------------------------------------------
// Softmax: read fp16 scores (half2), write fp32 alpha (scalar) + fp16 a2 (half2)
// ---------------------------------------------------------------------------
__global__ __launch_bounds__(256)
void softmax_rows(float* __restrict__ alpha) {
    const int row = blockIdx.x;
    const __half2* p2 = reinterpret_cast<const __half2*>(g_s16 + (size_t)row * L);
    float* pout = alpha + (size_t)row * L;
    const int tid = threadIdx.x;
    const int N2 = L / 2;   // 1250

    float2 vals[5];
    int cnt = 0;
    float mx = -INFINITY;
    for (int i = tid; i < N2; i += 256) {
        float2 v = __half22float2(p2[i]);
        vals[cnt++] = v;
        mx = fmaxf(mx, fmaxf(v.x, v.y));
    }
    __shared__ float red[256];
    red[tid] = mx; __syncthreads();
    for (int s = 128; s > 0; s >>= 1) {
        if (tid < s) red[tid] = fmaxf(red[tid], red[tid + s]);
        __syncthreads();
    }
    mx = red[0];
    __syncthreads();

    float sum = 0.f;
    for (int c = 0; c < cnt; c++) {
        vals[c].x = expf(vals[c].x - mx);
        vals[c].y = expf(vals[c].y - mx);
        sum += vals[c].x + vals[c].y;
    }
    red[tid] = sum; __syncthreads();
    for (int s = 128; s > 0; s >>= 1) {
        if (tid < s) red[tid] += red[tid + s];
        __syncthreads();
    }
    float inv = 1.0f / red[0];

    __half2* a2p = reinterpret_cast<__half2*>(g_a2 + (size_t)row * LP);
    cnt = 0;
    for (int i = tid; i < N2; i += 256) {
        float vx = vals[cnt].x * inv;
        float vy = vals[cnt].y * inv;
        cnt++;
        pout[2 * i]     = vx;
        pout[2 * i + 1] = vy;
        a2p[i] = __floats2half2_rn(vx, vy);
    }
    __half2 z = __floats2half2_rn(0.f, 0.f);
    for (int i = N2 + tid; i < LP / 2; i += 256)
        a2p[i] = z;
}

// ---------------------------------------------------------------------------
// Final: y from 4 partials + bias; BCE term; loss reduce
// ---------------------------------------------------------------------------
__global__ __launch_bounds__(256)
void final2(const float* __restrict__ fb,
            const float* __restrict__ target,
            float* __restrict__ out_y) {
    int r = blockIdx.x * 256 + threadIdx.x;
    if (r >= B * Y) return;
    const float* pp = g_ypart + (size_t)r * 4;
    float yv = (pp[0] + pp[1]) + (pp[2] + pp[3]) + fb[r % Y];
    out_y[r] = yv;
    float t = target[r];
    g_bce[r] = fmaxf(yv, 0.f) - yv * t + log1pf(expf(-fabsf(yv)));
}

__global__ __launch_bounds__(256)
void loss_reduce(float* __restrict__ out_loss) {
    __shared__ double sh[256];
    double s = 0.0;
    for (int i = threadIdx.x; i < B * Y; i += 256) s += (double)g_bce[i];
    sh[threadIdx.x] = s;
    __syncthreads();
    for (int st = 128; st > 0; st >>= 1) {
        if (threadIdx.x < st) sh[threadIdx.x] += sh[threadIdx.x + st];
        __syncthreads();
    }
    if (threadIdx.x == 0) out_loss[0] = (float)(sh[0] / (double)(B * Y));
}

// ---------------------------------------------------------------------------
// Launch. Output layout: [y (B*Y), loss (1), alpha (B*Y*L), m (B*Y*D)]
// ---------------------------------------------------------------------------
extern "C" void kernel_launch(void* const* d_in, const int* in_sizes, int n_in,
                              void* d_out, int out_size) {
    const float* x      = (const float*)d_in[0];
    const float* target = (const float*)d_in[1];
    // d_in[2] = text_inputs (unused)
    const float* Uw     = (const float*)d_in[3];
    const float* fw     = (const float*)d_in[4];
    const float* fb     = (const float*)d_in[5];

    float* out       = (float*)d_out;
    float* out_y     = out;
    float* out_loss  = out + (size_t)B * Y;
    float* out_alpha = out_loss + 1;
    float* out_m     = out_alpha + (size_t)B * Y * L;

    cudaFuncSetAttribute(gemm1_tc, cudaFuncAttributeMaxDynamicSharedMemorySize, SMEM_BYTES);
    cudaFuncSetAttribute(gemm2_tc, cudaFuncAttributeMaxDynamicSharedMemorySize, SMEM_BYTES);

    split_u<<<2048, 256>>>(Uw);
    fuse_x<<<dim3(LP / 32, D / 32, B), 256>>>(x);

    gemm1_tc<<<dim3((L + 127) / 128, (Y + 127) / 128, B), 256, SMEM_BYTES>>>();

    softmax_rows<<<B * Y, 256>>>(out_alpha);

    gemm2_tc<<<dim3(D / 128, (Y + 127) / 128, B), 256, SMEM_BYTES>>>(out_m, fw);

    final2<<<(B * Y + 255) / 256, 256>>>(fb, target, out_y);
    loss_reduce<<<1, 256>>>(out_loss);
}